// round 11
// baseline (speedup 1.0000x reference)
#include <cuda_runtime.h>
#include <cuda_bf16.h>
#include <cstdint>

#define NTOK 4096
#define HID  1024
#define NEXP 64
#define TOPK 8
#define IDIM 768
#define FLAT (NTOK*TOPK)
#define BM   128
#define MPAD 40960
#define MAXTILES 320

// ---------------- scratch ----------------
static __device__ float g_inter[(size_t)MPAD * IDIM];
static __device__ float g_y2[(size_t)MPAD * HID];
static __device__ float g_topkw[FLAT];
static __device__ int   g_flatexp[FLAT];
static __device__ int   g_invperm[FLAT];
static __device__ int   g_rowtok[MPAD];
static __device__ int   g_counts[NEXP];
static __device__ int   g_ctr[NEXP];
static __device__ int   g_offpad[NEXP];
static __device__ int   g_tile_e[MAXTILES];
static __device__ int   g_tile_r0[MAXTILES];
static __device__ int   g_ntiles;

// ---------------- helpers ----------------
__device__ __forceinline__ uint32_t smem_u32(const void* p) {
    uint32_t a;
    asm("{ .reg .u64 t; cvta.to.shared.u64 t, %1; cvt.u32.u64 %0, t; }" : "=r"(a) : "l"(p));
    return a;
}
#define STS128(a, v) \
    asm volatile("st.shared.v4.b32 [%0], {%1, %2, %3, %4};" \
        :: "r"(a), "r"((v).x), "r"((v).y), "r"((v).z), "r"((v).w) : "memory")

__device__ __forceinline__ void ldsm_x4(uint32_t (&r)[4], uint32_t addr) {
    asm volatile("ldmatrix.sync.aligned.m8n8.x4.shared.b16 {%0,%1,%2,%3}, [%4];"
        : "=r"(r[0]), "=r"(r[1]), "=r"(r[2]), "=r"(r[3]) : "r"(addr));
}
__device__ __forceinline__ void mma16816(float (&d)[4], const uint32_t (&a)[4], const uint32_t (&b)[2]) {
    asm volatile("mma.sync.aligned.m16n8k16.row.col.f32.bf16.bf16.f32 "
        "{%0,%1,%2,%3}, {%4,%5,%6,%7}, {%8,%9}, {%0,%1,%2,%3};"
        : "+f"(d[0]), "+f"(d[1]), "+f"(d[2]), "+f"(d[3])
        : "r"(a[0]), "r"(a[1]), "r"(a[2]), "r"(a[3]), "r"(b[0]), "r"(b[1]));
}

// fp32x8 -> bf16 hi/lo split
__device__ __forceinline__ void cvt8(const float4 f0, const float4 f1, uint4& H, uint4& L) {
    __nv_bfloat162 h;
    h = __float22bfloat162_rn(make_float2(f0.x, f0.y)); uint32_t u0 = *(uint32_t*)&h;
    h = __float22bfloat162_rn(make_float2(f0.z, f0.w)); uint32_t u1 = *(uint32_t*)&h;
    h = __float22bfloat162_rn(make_float2(f1.x, f1.y)); uint32_t u2 = *(uint32_t*)&h;
    h = __float22bfloat162_rn(make_float2(f1.z, f1.w)); uint32_t u3 = *(uint32_t*)&h;
    H = make_uint4(u0, u1, u2, u3);
    float l0 = f0.x - __uint_as_float(u0 << 16);
    float l1 = f0.y - __uint_as_float(u0 & 0xFFFF0000u);
    float l2 = f0.z - __uint_as_float(u1 << 16);
    float l3 = f0.w - __uint_as_float(u1 & 0xFFFF0000u);
    float l4 = f1.x - __uint_as_float(u2 << 16);
    float l5 = f1.y - __uint_as_float(u2 & 0xFFFF0000u);
    float l6 = f1.z - __uint_as_float(u3 << 16);
    float l7 = f1.w - __uint_as_float(u3 & 0xFFFF0000u);
    h = __float22bfloat162_rn(make_float2(l0, l1)); uint32_t v0 = *(uint32_t*)&h;
    h = __float22bfloat162_rn(make_float2(l2, l3)); uint32_t v1 = *(uint32_t*)&h;
    h = __float22bfloat162_rn(make_float2(l4, l5)); uint32_t v2 = *(uint32_t*)&h;
    h = __float22bfloat162_rn(make_float2(l6, l7)); uint32_t v3 = *(uint32_t*)&h;
    L = make_uint4(v0, v1, v2, v3);
}

// swizzled byte offset within a [rows][16 bf16] tile (32B rows, 2x16B chunks)
__device__ __forceinline__ uint32_t swz16(int row, int ch) {
    return (uint32_t)(row * 32 + ((ch ^ ((row >> 2) & 1)) << 4));
}

// ---------------- small kernels (gemm1 stays the 4th launch for ncu) ----------------
__global__ void initfill_kernel() {
    int i = blockIdx.x * 256 + threadIdx.x;
    if (i < MPAD) g_rowtok[i] = -1;
    if (i < NEXP) { g_counts[i] = 0; g_ctr[i] = 0; }
}

#define RT 8
__global__ void router_kernel(const float* __restrict__ x, const float* __restrict__ gate) {
    __shared__ float xs[RT][HID];
    __shared__ float lg[RT][NEXP];
    int t0 = blockIdx.x * RT;
    int tid = threadIdx.x;  // 256
    const float4* xsrc = (const float4*)(x + (size_t)t0 * HID);
    for (int i = tid; i < RT * HID / 4; i += 256) ((float4*)&xs[0][0])[i] = xsrc[i];
    __syncthreads();
    int tt = tid >> 5, lane = tid & 31;
    #pragma unroll
    for (int g = 0; g < 2; g++) {
        int e = g * 32 + lane;
        const float* gp = gate + (size_t)e * HID;
        float s = 0.f;
        #pragma unroll 4
        for (int k = 0; k < HID; k += 4) {
            float4 gv = *(const float4*)(gp + k);
            s += xs[tt][k] * gv.x + xs[tt][k+1] * gv.y + xs[tt][k+2] * gv.z + xs[tt][k+3] * gv.w;
        }
        lg[tt][e] = s;
    }
    __syncthreads();
    if (tid < RT) {
        int t = t0 + tid;
        float mx = lg[tid][0];
        #pragma unroll
        for (int e = 1; e < NEXP; e++) mx = fmaxf(mx, lg[tid][e]);
        unsigned long long taken = 0ull;
        float wsum = 0.f;
        int sel[TOPK]; float wv[TOPK];
        for (int k = 0; k < TOPK; k++) {
            int best = 0; float bv = -1e30f;
            for (int e = 0; e < NEXP; e++) {
                float v = lg[tid][e];
                if (!((taken >> e) & 1ull) && v > bv) { bv = v; best = e; }
            }
            taken |= 1ull << best;
            sel[k] = best;
            float w = expf(lg[tid][best] - mx);
            wv[k] = w; wsum += w;
            atomicAdd(&g_counts[best], 1);
        }
        float inv = 1.f / wsum;
        for (int k = 0; k < TOPK; k++) {
            g_topkw[t * TOPK + k]   = wv[k] * inv;
            g_flatexp[t * TOPK + k] = sel[k];
        }
    }
}

__global__ void metascatter_kernel() {
    int tid = threadIdx.x;   // 256
    if (tid == 0) {
        int nt = 0, cum = 0;
        for (int e = 0; e < NEXP; e++) {
            g_offpad[e] = cum;
            int c = g_counts[e];
            int t = (c + BM - 1) / BM;
            for (int j = 0; j < t; j++) { g_tile_e[nt] = e; g_tile_r0[nt] = cum + j * BM; nt++; }
            cum += t * BM;
        }
        g_ntiles = nt;
    }
    __syncthreads();
    for (int i = tid; i < FLAT; i += 256) {
        int e = g_flatexp[i];
        int dest = g_offpad[e] + atomicAdd(&g_ctr[e], 1);
        g_rowtok[dest] = i >> 3;
        g_invperm[i] = dest;
    }
}

// ---------------- grouped GEMM: CTA 128x256, warp tile 64x64, KC=16 double-buffer ----
// 8 warps (wm 0..1, wn 0..3). acc[4][8][4] = 128 fp32 regs.
// ILP fixes vs R10: (1) term-major mma order (8 independent mma between same-acc
// writes; per-acc term order HH,HL,LH preserved -> bit-identical), (2) software-
// pipelined B fragments (np+1's ldsm issued before np's mma block).

#define BUF_SZ  24576
#define OFF_ALO 4096
#define OFF_BHI 8192
#define OFF_BLO 16384
#define SMEM_BYTES 65536

template<bool FUSED>
__global__ void __launch_bounds__(256, 1) moe_gemm(const float* __restrict__ Ain,
                                                   const float* __restrict__ W) {
    constexpr int KDIM = FUSED ? HID : IDIM;   // 1024 / 768
    constexpr int NK   = KDIM / 16;            // 64 / 48
    int tile = blockIdx.x;
    if (tile >= g_ntiles) return;
    int e = g_tile_e[tile], row0 = g_tile_r0[tile], nb = blockIdx.y;

    extern __shared__ __align__(128) char smem[];
    uint32_t sb = smem_u32(smem);

    int tid = threadIdx.x, lane = tid & 31, wid = tid >> 5;
    int wm = wid >> 2, wn = wid & 3;

    // -------- copy mapping: A row = tid/2 (0..127); B rows = tid/2 and tid/2+128; ch = tid&1
    int rA = tid >> 1, chA = tid & 1;
    uint32_t soffA  = swz16(rA, chA);
    uint32_t soffB0 = swz16(rA, chA);
    uint32_t soffB1 = swz16(rA + 128, chA);

    const float* A = FUSED ? Ain : (const float*)g_inter;
    const float* aptr;
    if (FUSED) {
        int t0 = g_rowtok[row0 + rA];
        aptr = (t0 >= 0) ? A + (size_t)t0 * HID + chA * 8 : nullptr;
    } else {
        aptr = A + (size_t)(row0 + rA) * IDIM + chA * 8;
    }
    const float* Wb = W + (size_t)e * (size_t)(FUSED ? 2 * IDIM : HID) * KDIM;
    int wr0 = FUSED ? (nb * 128 + rA) : (nb * 256 + rA);
    int wr1 = FUSED ? (IDIM + nb * 128 + rA) : (nb * 256 + rA + 128);
    const float* bptr0 = Wb + (size_t)wr0 * KDIM + chA * 8;
    const float* bptr1 = Wb + (size_t)wr1 * KDIM + chA * 8;

    // B fragment row addressing (constant per lane)
    int brow_base = wn * 64 + (lane & 7) + ((lane >> 4) << 3);
    int bch = (lane >> 3) & 1;

    float acc[4][8][4];
    #pragma unroll
    for (int a = 0; a < 4; a++)
        #pragma unroll
        for (int b = 0; b < 8; b++)
            #pragma unroll
            for (int c = 0; c < 4; c++) acc[a][b][c] = 0.f;

    const float4 Z = make_float4(0.f, 0.f, 0.f, 0.f);
    float4 pa0, pa1, pb0, pb1, pb2, pb3;
    // prefetch kt = 0
    pa0 = aptr ? *(const float4*)(aptr)     : Z;
    pa1 = aptr ? *(const float4*)(aptr + 4) : Z;
    pb0 = *(const float4*)(bptr0);  pb1 = *(const float4*)(bptr0 + 4);
    pb2 = *(const float4*)(bptr1);  pb3 = *(const float4*)(bptr1 + 4);
    // fill buffer 0
    {
        uint4 H, L;
        cvt8(pa0, pa1, H, L); STS128(sb + soffA, H);            STS128(sb + OFF_ALO + soffA, L);
        cvt8(pb0, pb1, H, L); STS128(sb + OFF_BHI + soffB0, H); STS128(sb + OFF_BLO + soffB0, L);
        cvt8(pb2, pb3, H, L); STS128(sb + OFF_BHI + soffB1, H); STS128(sb + OFF_BLO + soffB1, L);
    }
    __syncthreads();

    #pragma unroll 1
    for (int kt = 0; kt < NK; kt++) {
        uint32_t cur = sb + (uint32_t)((kt & 1) * BUF_SZ);
        // issue next-tile LDGs early
        if (kt + 1 < NK) {
            int ko = (kt + 1) * 16;
            pa0 = aptr ? *(const float4*)(aptr + ko)     : Z;
            pa1 = aptr ? *(const float4*)(aptr + ko + 4) : Z;
            pb0 = *(const float4*)(bptr0 + ko);  pb1 = *(const float4*)(bptr0 + ko + 4);
            pb2 = *(const float4*)(bptr1 + ko);  pb3 = *(const float4*)(bptr1 + ko + 4);
        }

        // -------- compute one k=16 slab (warp tile 64x64), pipelined B frags
        {
            uint32_t aH[4][4], aL[4][4];
            #pragma unroll
            for (int mt = 0; mt < 4; mt++) {
                int row = wm * 64 + mt * 16 + (lane & 15);
                uint32_t ad = swz16(row, lane >> 4);
                ldsm_x4(aH[mt], cur + ad);
                ldsm_x4(aL[mt], cur + OFF_ALO + ad);
            }
            uint32_t tH[4], tL[4], nH[4], nL[4];
            {
                uint32_t bd = swz16(brow_base, bch);
                ldsm_x4(tH, cur + OFF_BHI + bd);
                ldsm_x4(tL, cur + OFF_BLO + bd);
            }
            #pragma unroll
            for (int np = 0; np < 4; np++) {
                if (np < 3) {
                    uint32_t bd = swz16(brow_base + (np + 1) * 16, bch);
                    ldsm_x4(nH, cur + OFF_BHI + bd);
                    ldsm_x4(nL, cur + OFF_BLO + bd);
                }
                uint32_t bH0[2] = {tH[0], tH[1]}, bH1[2] = {tH[2], tH[3]};
                uint32_t bL0[2] = {tL[0], tL[1]}, bL1[2] = {tL[2], tL[3]};
                // term-major: 8 independent mma between writes to the same acc;
                // per-acc order stays HH, HL, LH (bit-identical to R10).
                #pragma unroll
                for (int mt = 0; mt < 4; mt++) {
                    mma16816(acc[mt][2*np],   aH[mt], bH0);
                    mma16816(acc[mt][2*np+1], aH[mt], bH1);
                }
                #pragma unroll
                for (int mt = 0; mt < 4; mt++) {
                    mma16816(acc[mt][2*np],   aH[mt], bL0);
                    mma16816(acc[mt][2*np+1], aH[mt], bL1);
                }
                #pragma unroll
                for (int mt = 0; mt < 4; mt++) {
                    mma16816(acc[mt][2*np],   aL[mt], bH0);
                    mma16816(acc[mt][2*np+1], aL[mt], bH1);
                }
                #pragma unroll
                for (int i = 0; i < 4; i++) { tH[i] = nH[i]; tL[i] = nL[i]; }
            }
        }

        // stage next slab into the other buffer
        if (kt + 1 < NK) {
            uint32_t nxt = sb + (uint32_t)(((kt + 1) & 1) * BUF_SZ);
            uint4 H, L;
            cvt8(pa0, pa1, H, L); STS128(nxt + soffA, H);            STS128(nxt + OFF_ALO + soffA, L);
            cvt8(pb0, pb1, H, L); STS128(nxt + OFF_BHI + soffB0, H); STS128(nxt + OFF_BLO + soffB0, L);
            cvt8(pb2, pb3, H, L); STS128(nxt + OFF_BHI + soffB1, H); STS128(nxt + OFF_BLO + soffB1, L);
        }
        __syncthreads();
    }

    if (FUSED) {
        float* sUp = (float*)smem;   // [128][128] f32 = 64KB
        if (wn >= 2) {               // up warps: cols 128..255
            #pragma unroll
            for (int mt = 0; mt < 4; mt++)
                #pragma unroll
                for (int nt = 0; nt < 8; nt++) {
                    int m = wm * 64 + mt * 16 + (lane >> 2);
                    int c = (wn - 2) * 64 + nt * 8 + (lane & 3) * 2;
                    sUp[m * 128 + c]           = acc[mt][nt][0];
                    sUp[m * 128 + c + 1]       = acc[mt][nt][1];
                    sUp[(m + 8) * 128 + c]     = acc[mt][nt][2];
                    sUp[(m + 8) * 128 + c + 1] = acc[mt][nt][3];
                }
        }
        __syncthreads();
        if (wn < 2) {                // gate warps: cols 0..127
            #pragma unroll
            for (int mt = 0; mt < 4; mt++)
                #pragma unroll
                for (int nt = 0; nt < 8; nt++) {
                    int m = wm * 64 + mt * 16 + (lane >> 2);
                    int c = wn * 64 + nt * 8 + (lane & 3) * 2;
                    #pragma unroll
                    for (int h = 0; h < 2; h++) {
                        int mm = m + h * 8;
                        float g0 = acc[mt][nt][h * 2], g1 = acc[mt][nt][h * 2 + 1];
                        float u0 = sUp[mm * 128 + c], u1 = sUp[mm * 128 + c + 1];
                        float2 o;
                        o.x = g0 / (1.f + expf(-g0)) * u0;
                        o.y = g1 / (1.f + expf(-g1)) * u1;
                        *(float2*)&g_inter[(size_t)(row0 + mm) * IDIM + nb * 128 + c] = o;
                    }
                }
        }
    } else {
        #pragma unroll
        for (int mt = 0; mt < 4; mt++)
            #pragma unroll
            for (int nt = 0; nt < 8; nt++) {
                int m = row0 + wm * 64 + mt * 16 + (lane >> 2);
                int c = nb * 256 + wn * 64 + nt * 8 + (lane & 3) * 2;
                *(float2*)&g_y2[(size_t)m * HID + c]       = make_float2(acc[mt][nt][0], acc[mt][nt][1]);
                *(float2*)&g_y2[(size_t)(m + 8) * HID + c] = make_float2(acc[mt][nt][2], acc[mt][nt][3]);
            }
    }
}

// ---------------- combine ----------------
__global__ void combine_kernel(float* __restrict__ out) {
    __shared__ float w[TOPK];
    __shared__ int rows[TOPK];
    int t = blockIdx.x;
    int tid = threadIdx.x;
    if (tid < TOPK) {
        w[tid]    = g_topkw[t * TOPK + tid];
        rows[tid] = g_invperm[t * TOPK + tid];
    }
    __syncthreads();
    float4 acc = make_float4(0.f, 0.f, 0.f, 0.f);
    #pragma unroll
    for (int k = 0; k < TOPK; k++) {
        const float4 v = *(const float4*)&g_y2[(size_t)rows[k] * HID + (tid << 2)];
        float wk = w[k];
        acc.x += wk * v.x; acc.y += wk * v.y; acc.z += wk * v.z; acc.w += wk * v.w;
    }
    *(float4*)(out + (size_t)t * HID + (tid << 2)) = acc;
}

// ---------------- launch ----------------
extern "C" void kernel_launch(void* const* d_in, const int* in_sizes, int n_in,
                              void* d_out, int out_size) {
    const float* x    = (const float*)d_in[0];
    const float* gate = (const float*)d_in[1];
    const float* gup  = (const float*)d_in[2];
    const float* dwn  = (const float*)d_in[3];
    float* out = (float*)d_out;

    cudaFuncSetAttribute(moe_gemm<true>,  cudaFuncAttributeMaxDynamicSharedMemorySize, SMEM_BYTES);
    cudaFuncSetAttribute(moe_gemm<false>, cudaFuncAttributeMaxDynamicSharedMemorySize, SMEM_BYTES);

    initfill_kernel<<<(MPAD + 255) / 256, 256>>>();                     // launch 0
    router_kernel<<<NTOK / RT, 256>>>(x, gate);                         // launch 1
    metascatter_kernel<<<1, 256>>>();                                   // launch 2
    moe_gemm<true><<<dim3(MAXTILES, IDIM / 128), 256, SMEM_BYTES>>>(x, gup);       // launch 3 (profiled)
    moe_gemm<false><<<dim3(MAXTILES, HID / 256), 256, SMEM_BYTES>>>(nullptr, dwn); // launch 4
    combine_kernel<<<NTOK, 256>>>(out);                                 // launch 5
}

// round 12
// speedup vs baseline: 1.2685x; 1.2685x over previous
#include <cuda_runtime.h>
#include <cuda_fp16.h>
#include <cstdint>

#define NTOK 4096
#define HID  1024
#define NEXP 64
#define TOPK 8
#define IDIM 768
#define FLAT (NTOK*TOPK)
#define BM   128
#define MPAD 40960
#define MAXTILES 320

// ---------------- scratch ----------------
static __device__ float g_inter[(size_t)MPAD * IDIM];
static __device__ float g_y2[(size_t)MPAD * HID];
static __device__ float g_topkw[FLAT];
static __device__ int   g_flatexp[FLAT];
static __device__ int   g_invperm[FLAT];
static __device__ int   g_rowtok[MPAD];
static __device__ int   g_counts[NEXP];
static __device__ int   g_ctr[NEXP];
static __device__ int   g_offpad[NEXP];
static __device__ int   g_tile_e[MAXTILES];
static __device__ int   g_tile_r0[MAXTILES];
static __device__ int   g_ntiles;

// ---------------- helpers ----------------
__device__ __forceinline__ uint32_t smem_u32(const void* p) {
    uint32_t a;
    asm("{ .reg .u64 t; cvta.to.shared.u64 t, %1; cvt.u32.u64 %0, t; }" : "=r"(a) : "l"(p));
    return a;
}
#define STS128(a, v) \
    asm volatile("st.shared.v4.b32 [%0], {%1, %2, %3, %4};" \
        :: "r"(a), "r"((v).x), "r"((v).y), "r"((v).z), "r"((v).w) : "memory")

__device__ __forceinline__ void ldsm_x4(uint32_t (&r)[4], uint32_t addr) {
    asm volatile("ldmatrix.sync.aligned.m8n8.x4.shared.b16 {%0,%1,%2,%3}, [%4];"
        : "=r"(r[0]), "=r"(r[1]), "=r"(r[2]), "=r"(r[3]) : "r"(addr));
}
__device__ __forceinline__ void mma16816(float (&d)[4], const uint32_t (&a)[4], const uint32_t (&b)[2]) {
    asm volatile("mma.sync.aligned.m16n8k16.row.col.f32.f16.f16.f32 "
        "{%0,%1,%2,%3}, {%4,%5,%6,%7}, {%8,%9}, {%0,%1,%2,%3};"
        : "+f"(d[0]), "+f"(d[1]), "+f"(d[2]), "+f"(d[3])
        : "r"(a[0]), "r"(a[1]), "r"(a[2]), "r"(a[3]), "r"(b[0]), "r"(b[1]));
}

// 8 fp32 -> 8 fp16 (packed), single rounding
__device__ __forceinline__ void cvt8h(const float4 f0, const float4 f1, uint4& H) {
    __half2 h;
    h = __floats2half2_rn(f0.x, f0.y); H.x = *(uint32_t*)&h;
    h = __floats2half2_rn(f0.z, f0.w); H.y = *(uint32_t*)&h;
    h = __floats2half2_rn(f1.x, f1.y); H.z = *(uint32_t*)&h;
    h = __floats2half2_rn(f1.z, f1.w); H.w = *(uint32_t*)&h;
}
// 8 fp32 -> fp16 hi + fp16 lo (residual), near-exact 2-term representation
__device__ __forceinline__ void cvt8hs(const float4 f0, const float4 f1, uint4& H, uint4& L) {
    float f[8] = {f0.x, f0.y, f0.z, f0.w, f1.x, f1.y, f1.z, f1.w};
    uint32_t hr[4], lr[4];
    #pragma unroll
    for (int i = 0; i < 4; i++) {
        __half a = __float2half_rn(f[2*i]);
        __half b = __float2half_rn(f[2*i+1]);
        __half2 hp = __halves2half2(a, b);
        hr[i] = *(uint32_t*)&hp;
        __half2 lp = __floats2half2_rn(f[2*i]   - __half2float(a),
                                       f[2*i+1] - __half2float(b));
        lr[i] = *(uint32_t*)&lp;
    }
    H = make_uint4(hr[0], hr[1], hr[2], hr[3]);
    L = make_uint4(lr[0], lr[1], lr[2], lr[3]);
}

// swizzled byte offset within a [rows][16 fp16] tile (32B rows, 2x16B chunks)
__device__ __forceinline__ uint32_t swz16(int row, int ch) {
    return (uint32_t)(row * 32 + ((ch ^ ((row >> 2) & 1)) << 4));
}

// ---------------- small kernels (gemm1 stays the 4th launch for ncu) ----------------
__global__ void initfill_kernel() {
    int i = blockIdx.x * 256 + threadIdx.x;
    if (i < MPAD) g_rowtok[i] = -1;
    if (i < NEXP) { g_counts[i] = 0; g_ctr[i] = 0; }
}

#define RT 8
__global__ void router_kernel(const float* __restrict__ x, const float* __restrict__ gate) {
    __shared__ float xs[RT][HID];
    __shared__ float lg[RT][NEXP];
    int t0 = blockIdx.x * RT;
    int tid = threadIdx.x;  // 256
    const float4* xsrc = (const float4*)(x + (size_t)t0 * HID);
    for (int i = tid; i < RT * HID / 4; i += 256) ((float4*)&xs[0][0])[i] = xsrc[i];
    __syncthreads();
    int tt = tid >> 5, lane = tid & 31;
    #pragma unroll
    for (int g = 0; g < 2; g++) {
        int e = g * 32 + lane;
        const float* gp = gate + (size_t)e * HID;
        float s = 0.f;
        #pragma unroll 4
        for (int k = 0; k < HID; k += 4) {
            float4 gv = *(const float4*)(gp + k);
            s += xs[tt][k] * gv.x + xs[tt][k+1] * gv.y + xs[tt][k+2] * gv.z + xs[tt][k+3] * gv.w;
        }
        lg[tt][e] = s;
    }
    __syncthreads();
    if (tid < RT) {
        int t = t0 + tid;
        float mx = lg[tid][0];
        #pragma unroll
        for (int e = 1; e < NEXP; e++) mx = fmaxf(mx, lg[tid][e]);
        unsigned long long taken = 0ull;
        float wsum = 0.f;
        int sel[TOPK]; float wv[TOPK];
        for (int k = 0; k < TOPK; k++) {
            int best = 0; float bv = -1e30f;
            for (int e = 0; e < NEXP; e++) {
                float v = lg[tid][e];
                if (!((taken >> e) & 1ull) && v > bv) { bv = v; best = e; }
            }
            taken |= 1ull << best;
            sel[k] = best;
            float w = expf(lg[tid][best] - mx);
            wv[k] = w; wsum += w;
            atomicAdd(&g_counts[best], 1);
        }
        float inv = 1.f / wsum;
        for (int k = 0; k < TOPK; k++) {
            g_topkw[t * TOPK + k]   = wv[k] * inv;
            g_flatexp[t * TOPK + k] = sel[k];
        }
    }
}

__global__ void metascatter_kernel() {
    int tid = threadIdx.x;   // 256
    if (tid == 0) {
        int nt = 0, cum = 0;
        for (int e = 0; e < NEXP; e++) {
            g_offpad[e] = cum;
            int c = g_counts[e];
            int t = (c + BM - 1) / BM;
            for (int j = 0; j < t; j++) { g_tile_e[nt] = e; g_tile_r0[nt] = cum + j * BM; nt++; }
            cum += t * BM;
        }
        g_ntiles = nt;
    }
    __syncthreads();
    for (int i = tid; i < FLAT; i += 256) {
        int e = g_flatexp[i];
        int dest = g_offpad[e] + atomicAdd(&g_ctr[e], 1);
        g_rowtok[dest] = i >> 3;
        g_invperm[i] = dest;
    }
}

// ---------------- grouped GEMM: fp16 2-term (A single, B hi/lo), KC=16, 2 CTA/SM ----
// CTA: 256 thr = 8 warps (2x4), tile M=128 x N=128, warp tile 64x32.
// Buffer = A(4K)|Bhi(4K)|Blo(4K) = 12KB; double-buffered within 32KB dynamic smem.
// D = A_f16 * Bhi + A_f16 * Blo   (B split is near-exact; error = A rounding ~2.8e-4)

#define BUF_SZ  12288
#define OFF_BHI 4096
#define OFF_BLO 8192
#define SMEM_BYTES 32768

template<bool FUSED>
__global__ void __launch_bounds__(256, 2) moe_gemm(const float* __restrict__ Ain,
                                                   const float* __restrict__ W) {
    constexpr int KDIM = FUSED ? HID : IDIM;   // 1024 / 768
    constexpr int NK   = KDIM / 16;            // 64 / 48
    int tile = blockIdx.x;
    if (tile >= g_ntiles) return;
    int e = g_tile_e[tile], row0 = g_tile_r0[tile], nb = blockIdx.y;

    extern __shared__ __align__(128) char smem[];
    uint32_t sb = smem_u32(smem);

    int tid = threadIdx.x, lane = tid & 31, wid = tid >> 5;
    int wm = wid >> 2, wn = wid & 3;

    // -------- copy mapping: row = tid/2 (0..127), ch = tid&1 (8 fp32 -> one 16B fp16 chunk)
    int rA = tid >> 1, chA = tid & 1;
    uint32_t soff = swz16(rA, chA);

    const float* A = FUSED ? Ain : (const float*)g_inter;
    const float* aptr;
    if (FUSED) {
        int t0 = g_rowtok[row0 + rA];
        aptr = (t0 >= 0) ? A + (size_t)t0 * HID + chA * 8 : nullptr;
    } else {
        aptr = A + (size_t)(row0 + rA) * IDIM + chA * 8;
    }
    const float* Wb = W + (size_t)e * (size_t)(FUSED ? 2 * IDIM : HID) * KDIM;
    int wr = FUSED ? ((rA < 64) ? nb * 64 + rA : IDIM + nb * 64 + (rA - 64))
                   : nb * 128 + rA;
    const float* bptr = Wb + (size_t)wr * KDIM + chA * 8;

    float acc[4][4][4];
    #pragma unroll
    for (int a = 0; a < 4; a++)
        #pragma unroll
        for (int b = 0; b < 4; b++)
            #pragma unroll
            for (int c = 0; c < 4; c++) acc[a][b][c] = 0.f;

    const float4 Z = make_float4(0.f, 0.f, 0.f, 0.f);
    float4 pa0, pa1, pb0, pb1;
    // prefetch kt = 0
    pa0 = aptr ? *(const float4*)(aptr)     : Z;
    pa1 = aptr ? *(const float4*)(aptr + 4) : Z;
    pb0 = *(const float4*)(bptr);
    pb1 = *(const float4*)(bptr + 4);
    // fill buffer 0
    {
        uint4 H, L;
        cvt8h(pa0, pa1, H);    STS128(sb + soff, H);
        cvt8hs(pb0, pb1, H, L); STS128(sb + OFF_BHI + soff, H); STS128(sb + OFF_BLO + soff, L);
    }
    __syncthreads();

    #pragma unroll 1
    for (int kt = 0; kt < NK; kt++) {
        uint32_t cur = sb + (uint32_t)((kt & 1) * BUF_SZ);
        // issue next-tile LDGs early
        if (kt + 1 < NK) {
            int ko = (kt + 1) * 16;
            pa0 = aptr ? *(const float4*)(aptr + ko)     : Z;
            pa1 = aptr ? *(const float4*)(aptr + ko + 4) : Z;
            pb0 = *(const float4*)(bptr + ko);
            pb1 = *(const float4*)(bptr + ko + 4);
        }

        // -------- compute one k=16 slab (warp tile 64x32, 2-term fp16)
        {
            uint32_t aH[4][4];
            #pragma unroll
            for (int mt = 0; mt < 4; mt++) {
                int row = wm * 64 + mt * 16 + (lane & 15);
                uint32_t ad = swz16(row, lane >> 4);
                ldsm_x4(aH[mt], cur + ad);
            }
            #pragma unroll
            for (int np = 0; np < 2; np++) {
                int row = wn * 32 + np * 16 + (lane & 7) + ((lane >> 4) << 3);
                uint32_t bd = swz16(row, (lane >> 3) & 1);
                uint32_t tH[4], tL[4];
                ldsm_x4(tH, cur + OFF_BHI + bd);
                ldsm_x4(tL, cur + OFF_BLO + bd);
                uint32_t bH0[2] = {tH[0], tH[1]}, bH1[2] = {tH[2], tH[3]};
                uint32_t bL0[2] = {tL[0], tL[1]}, bL1[2] = {tL[2], tL[3]};
                #pragma unroll
                for (int mt = 0; mt < 4; mt++) {
                    mma16816(acc[mt][2*np],   aH[mt], bH0);
                    mma16816(acc[mt][2*np+1], aH[mt], bH1);
                }
                #pragma unroll
                for (int mt = 0; mt < 4; mt++) {
                    mma16816(acc[mt][2*np],   aH[mt], bL0);
                    mma16816(acc[mt][2*np+1], aH[mt], bL1);
                }
            }
        }

        // stage next slab into the other buffer
        if (kt + 1 < NK) {
            uint32_t nxt = sb + (uint32_t)(((kt + 1) & 1) * BUF_SZ);
            uint4 H, L;
            cvt8h(pa0, pa1, H);    STS128(nxt + soff, H);
            cvt8hs(pb0, pb1, H, L); STS128(nxt + OFF_BHI + soff, H); STS128(nxt + OFF_BLO + soff, L);
        }
        __syncthreads();
    }

    if (FUSED) {
        float* sUp = (float*)smem;   // [128][64] f32 = 32KB (fits dynamic smem exactly)
        if (wn >= 2) {
            #pragma unroll
            for (int mt = 0; mt < 4; mt++)
                #pragma unroll
                for (int nt = 0; nt < 4; nt++) {
                    int m = wm * 64 + mt * 16 + (lane >> 2);
                    int c = (wn - 2) * 32 + nt * 8 + (lane & 3) * 2;
                    sUp[m * 64 + c]           = acc[mt][nt][0];
                    sUp[m * 64 + c + 1]       = acc[mt][nt][1];
                    sUp[(m + 8) * 64 + c]     = acc[mt][nt][2];
                    sUp[(m + 8) * 64 + c + 1] = acc[mt][nt][3];
                }
        }
        __syncthreads();
        if (wn < 2) {
            #pragma unroll
            for (int mt = 0; mt < 4; mt++)
                #pragma unroll
                for (int nt = 0; nt < 4; nt++) {
                    int m = wm * 64 + mt * 16 + (lane >> 2);
                    int c = wn * 32 + nt * 8 + (lane & 3) * 2;
                    #pragma unroll
                    for (int h = 0; h < 2; h++) {
                        int mm = m + h * 8;
                        float g0 = acc[mt][nt][h * 2], g1 = acc[mt][nt][h * 2 + 1];
                        float u0 = sUp[mm * 64 + c], u1 = sUp[mm * 64 + c + 1];
                        float2 o;
                        o.x = g0 / (1.f + expf(-g0)) * u0;
                        o.y = g1 / (1.f + expf(-g1)) * u1;
                        *(float2*)&g_inter[(size_t)(row0 + mm) * IDIM + nb * 64 + c] = o;
                    }
                }
        }
    } else {
        #pragma unroll
        for (int mt = 0; mt < 4; mt++)
            #pragma unroll
            for (int nt = 0; nt < 4; nt++) {
                int m = row0 + wm * 64 + mt * 16 + (lane >> 2);
                int c = nb * 128 + wn * 32 + nt * 8 + (lane & 3) * 2;
                *(float2*)&g_y2[(size_t)m * HID + c]       = make_float2(acc[mt][nt][0], acc[mt][nt][1]);
                *(float2*)&g_y2[(size_t)(m + 8) * HID + c] = make_float2(acc[mt][nt][2], acc[mt][nt][3]);
            }
    }
}

// ---------------- combine ----------------
__global__ void combine_kernel(float* __restrict__ out) {
    __shared__ float w[TOPK];
    __shared__ int rows[TOPK];
    int t = blockIdx.x;
    int tid = threadIdx.x;
    if (tid < TOPK) {
        w[tid]    = g_topkw[t * TOPK + tid];
        rows[tid] = g_invperm[t * TOPK + tid];
    }
    __syncthreads();
    float4 acc = make_float4(0.f, 0.f, 0.f, 0.f);
    #pragma unroll
    for (int k = 0; k < TOPK; k++) {
        const float4 v = *(const float4*)&g_y2[(size_t)rows[k] * HID + (tid << 2)];
        float wk = w[k];
        acc.x += wk * v.x; acc.y += wk * v.y; acc.z += wk * v.z; acc.w += wk * v.w;
    }
    *(float4*)(out + (size_t)t * HID + (tid << 2)) = acc;
}

// ---------------- launch ----------------
extern "C" void kernel_launch(void* const* d_in, const int* in_sizes, int n_in,
                              void* d_out, int out_size) {
    const float* x    = (const float*)d_in[0];
    const float* gate = (const float*)d_in[1];
    const float* gup  = (const float*)d_in[2];
    const float* dwn  = (const float*)d_in[3];
    float* out = (float*)d_out;

    cudaFuncSetAttribute(moe_gemm<true>,  cudaFuncAttributeMaxDynamicSharedMemorySize, SMEM_BYTES);
    cudaFuncSetAttribute(moe_gemm<false>, cudaFuncAttributeMaxDynamicSharedMemorySize, SMEM_BYTES);

    initfill_kernel<<<(MPAD + 255) / 256, 256>>>();                     // launch 0
    router_kernel<<<NTOK / RT, 256>>>(x, gate);                         // launch 1
    metascatter_kernel<<<1, 256>>>();                                   // launch 2
    moe_gemm<true><<<dim3(MAXTILES, IDIM / 64), 256, SMEM_BYTES>>>(x, gup);        // launch 3 (profiled)
    moe_gemm<false><<<dim3(MAXTILES, HID / 128), 256, SMEM_BYTES>>>(nullptr, dwn); // launch 4
    combine_kernel<<<NTOK, 256>>>(out);                                 // launch 5
}

// round 13
// speedup vs baseline: 1.4079x; 1.1099x over previous
#include <cuda_runtime.h>
#include <cuda_fp16.h>
#include <cstdint>

#define NTOK 4096
#define HID  1024
#define NEXP 64
#define TOPK 8
#define IDIM 768
#define FLAT (NTOK*TOPK)
#define BM   128
#define MPAD 40960
#define MAXTILES 320

// ---------------- scratch ----------------
static __device__ float g_inter[(size_t)MPAD * IDIM];
static __device__ float g_y2[(size_t)MPAD * HID];
static __device__ float g_topkw[FLAT];
static __device__ int   g_flatexp[FLAT];
static __device__ int   g_invperm[FLAT];
static __device__ int   g_rowtok[MPAD];
static __device__ int   g_counts[NEXP];
static __device__ int   g_ctr[NEXP];
static __device__ int   g_offpad[NEXP];
static __device__ int   g_tile_e[MAXTILES];
static __device__ int   g_tile_r0[MAXTILES];
static __device__ int   g_ntiles;

// ---------------- helpers ----------------
__device__ __forceinline__ uint32_t smem_u32(const void* p) {
    uint32_t a;
    asm("{ .reg .u64 t; cvta.to.shared.u64 t, %1; cvt.u32.u64 %0, t; }" : "=r"(a) : "l"(p));
    return a;
}
#define STS64(a, v0, v1) \
    asm volatile("st.shared.v2.b32 [%0], {%1, %2};" :: "r"(a), "r"(v0), "r"(v1) : "memory")

__device__ __forceinline__ void ldsm_x4(uint32_t (&r)[4], uint32_t addr) {
    asm volatile("ldmatrix.sync.aligned.m8n8.x4.shared.b16 {%0,%1,%2,%3}, [%4];"
        : "=r"(r[0]), "=r"(r[1]), "=r"(r[2]), "=r"(r[3]) : "r"(addr));
}
__device__ __forceinline__ void mma16816(float (&d)[4], const uint32_t (&a)[4], const uint32_t (&b)[2]) {
    asm volatile("mma.sync.aligned.m16n8k16.row.col.f32.f16.f16.f32 "
        "{%0,%1,%2,%3}, {%4,%5,%6,%7}, {%8,%9}, {%0,%1,%2,%3};"
        : "+f"(d[0]), "+f"(d[1]), "+f"(d[2]), "+f"(d[3])
        : "r"(a[0]), "r"(a[1]), "r"(a[2]), "r"(a[3]), "r"(b[0]), "r"(b[1]));
}

// 4 fp32 -> 4 fp16 packed (2x u32), single rounding
__device__ __forceinline__ void cvt4h(const float4 f, uint32_t& h0, uint32_t& h1) {
    __half2 h;
    h = __floats2half2_rn(f.x, f.y); h0 = *(uint32_t*)&h;
    h = __floats2half2_rn(f.z, f.w); h1 = *(uint32_t*)&h;
}
// 4 fp32 -> fp16 hi + fp16 lo (residual)
__device__ __forceinline__ void cvt4hs(const float4 f, uint32_t& h0, uint32_t& h1,
                                       uint32_t& l0, uint32_t& l1) {
    float v[4] = {f.x, f.y, f.z, f.w};
    uint32_t hr[2], lr[2];
    #pragma unroll
    for (int i = 0; i < 2; i++) {
        __half a = __float2half_rn(v[2*i]);
        __half b = __float2half_rn(v[2*i+1]);
        __half2 hp = __halves2half2(a, b);
        hr[i] = *(uint32_t*)&hp;
        __half2 lp = __floats2half2_rn(v[2*i]   - __half2float(a),
                                       v[2*i+1] - __half2float(b));
        lr[i] = *(uint32_t*)&lp;
    }
    h0 = hr[0]; h1 = hr[1]; l0 = lr[0]; l1 = lr[1];
}

// swizzled byte offset within a [rows][16 fp16] tile (32B rows, 2x16B chunks)
__device__ __forceinline__ uint32_t swz16(int row, int ch) {
    return (uint32_t)(row * 32 + ((ch ^ ((row >> 2) & 1)) << 4));
}

// ---------------- small kernels (gemm1 stays the 4th launch for ncu) ----------------
__global__ void initfill_kernel() {
    int i = blockIdx.x * 256 + threadIdx.x;
    if (i < MPAD) g_rowtok[i] = -1;
    if (i < NEXP) { g_counts[i] = 0; g_ctr[i] = 0; }
}

#define RT 8
__global__ void router_kernel(const float* __restrict__ x, const float* __restrict__ gate) {
    __shared__ float xs[RT][HID];
    __shared__ float lg[RT][NEXP];
    int t0 = blockIdx.x * RT;
    int tid = threadIdx.x;  // 256
    const float4* xsrc = (const float4*)(x + (size_t)t0 * HID);
    for (int i = tid; i < RT * HID / 4; i += 256) ((float4*)&xs[0][0])[i] = xsrc[i];
    __syncthreads();
    int tt = tid >> 5, lane = tid & 31;
    #pragma unroll
    for (int g = 0; g < 2; g++) {
        int e = g * 32 + lane;
        const float* gp = gate + (size_t)e * HID;
        float s = 0.f;
        #pragma unroll 4
        for (int k = 0; k < HID; k += 4) {
            float4 gv = *(const float4*)(gp + k);
            s += xs[tt][k] * gv.x + xs[tt][k+1] * gv.y + xs[tt][k+2] * gv.z + xs[tt][k+3] * gv.w;
        }
        lg[tt][e] = s;
    }
    __syncthreads();
    if (tid < RT) {
        int t = t0 + tid;
        float mx = lg[tid][0];
        #pragma unroll
        for (int e = 1; e < NEXP; e++) mx = fmaxf(mx, lg[tid][e]);
        unsigned long long taken = 0ull;
        float wsum = 0.f;
        int sel[TOPK]; float wv[TOPK];
        for (int k = 0; k < TOPK; k++) {
            int best = 0; float bv = -1e30f;
            for (int e = 0; e < NEXP; e++) {
                float v = lg[tid][e];
                if (!((taken >> e) & 1ull) && v > bv) { bv = v; best = e; }
            }
            taken |= 1ull << best;
            sel[k] = best;
            float w = expf(lg[tid][best] - mx);
            wv[k] = w; wsum += w;
            atomicAdd(&g_counts[best], 1);
        }
        float inv = 1.f / wsum;
        for (int k = 0; k < TOPK; k++) {
            g_topkw[t * TOPK + k]   = wv[k] * inv;
            g_flatexp[t * TOPK + k] = sel[k];
        }
    }
}

__global__ void metascatter_kernel() {
    int tid = threadIdx.x;   // 256
    if (tid == 0) {
        int nt = 0, cum = 0;
        for (int e = 0; e < NEXP; e++) {
            g_offpad[e] = cum;
            int c = g_counts[e];
            int t = (c + BM - 1) / BM;
            for (int j = 0; j < t; j++) { g_tile_e[nt] = e; g_tile_r0[nt] = cum + j * BM; nt++; }
            cum += t * BM;
        }
        g_ntiles = nt;
    }
    __syncthreads();
    for (int i = tid; i < FLAT; i += 256) {
        int e = g_flatexp[i];
        int dest = g_offpad[e] + atomicAdd(&g_ctr[e], 1);
        g_rowtok[dest] = i >> 3;
        g_invperm[i] = dest;
    }
}

// ---------------- grouped GEMM: fp16 2-term, coalesced copy, KC=16, 2 CTA/SM ----------
// CTA: 256 thr = 8 warps (2x4), tile M=128 x N=128, warp tile 64x32.
// Copy mapping: 4 consecutive lanes cover one row's 64B (1 line-touch per row):
//   slot0: row = tid/4 (0..63), slot1: row = 64 + tid/4; ch16 = tid&3.
// Buffer = A(4K)|Bhi(4K)|Blo(4K) = 12KB; double-buffered in 32KB dynamic smem.
// D = A_f16 * Bhi + A_f16 * Blo

#define BUF_SZ  12288
#define OFF_BHI 4096
#define OFF_BLO 8192
#define SMEM_BYTES 32768

template<bool FUSED>
__global__ void __launch_bounds__(256, 2) moe_gemm(const float* __restrict__ Ain,
                                                   const float* __restrict__ W) {
    constexpr int KDIM = FUSED ? HID : IDIM;   // 1024 / 768
    constexpr int NK   = KDIM / 16;            // 64 / 48
    int tile = blockIdx.x;
    if (tile >= g_ntiles) return;
    int e = g_tile_e[tile], row0 = g_tile_r0[tile], nb = blockIdx.y;

    extern __shared__ __align__(128) char smem[];
    uint32_t sb = smem_u32(smem);

    int tid = threadIdx.x, lane = tid & 31, wid = tid >> 5;
    int wm = wid >> 2, wn = wid & 3;

    // -------- copy mapping: rows r0 = tid/4, r1 = 64 + tid/4; ch16 = tid&3 (16B units)
    int r0 = tid >> 2, r1 = r0 + 64, ch = tid & 3;
    // smem: 8B half-chunk address within [128][16 fp16] tile
    uint32_t soff0 = swz16(r0, ch >> 1) + (uint32_t)((ch & 1) * 8);
    uint32_t soff1 = swz16(r1, ch >> 1) + (uint32_t)((ch & 1) * 8);

    const float* A = FUSED ? Ain : (const float*)g_inter;
    const float *aptr0, *aptr1;
    if (FUSED) {
        int t0 = g_rowtok[row0 + r0], t1 = g_rowtok[row0 + r1];
        aptr0 = (t0 >= 0) ? A + (size_t)t0 * HID + ch * 4 : nullptr;
        aptr1 = (t1 >= 0) ? A + (size_t)t1 * HID + ch * 4 : nullptr;
    } else {
        aptr0 = A + (size_t)(row0 + r0) * IDIM + ch * 4;
        aptr1 = A + (size_t)(row0 + r1) * IDIM + ch * 4;
    }
    const float* Wb = W + (size_t)e * (size_t)(FUSED ? 2 * IDIM : HID) * KDIM;
    int wr0 = FUSED ? (nb * 64 + r0) : (nb * 128 + r0);            // r0 in 0..63
    int wr1 = FUSED ? (IDIM + nb * 64 + (r1 - 64)) : (nb * 128 + r1);
    const float* bptr0 = Wb + (size_t)wr0 * KDIM + ch * 4;
    const float* bptr1 = Wb + (size_t)wr1 * KDIM + ch * 4;

    float acc[4][4][4];
    #pragma unroll
    for (int a = 0; a < 4; a++)
        #pragma unroll
        for (int b = 0; b < 4; b++)
            #pragma unroll
            for (int c = 0; c < 4; c++) acc[a][b][c] = 0.f;

    const float4 Z = make_float4(0.f, 0.f, 0.f, 0.f);
    float4 pa0, pa1, pb0, pb1;
    // prefetch kt = 0
    pa0 = aptr0 ? *(const float4*)(aptr0) : Z;
    pa1 = aptr1 ? *(const float4*)(aptr1) : Z;
    pb0 = *(const float4*)(bptr0);
    pb1 = *(const float4*)(bptr1);
    // fill buffer 0
    {
        uint32_t h0, h1, l0, l1;
        cvt4h(pa0, h0, h1);          STS64(sb + soff0, h0, h1);
        cvt4h(pa1, h0, h1);          STS64(sb + soff1, h0, h1);
        cvt4hs(pb0, h0, h1, l0, l1); STS64(sb + OFF_BHI + soff0, h0, h1); STS64(sb + OFF_BLO + soff0, l0, l1);
        cvt4hs(pb1, h0, h1, l0, l1); STS64(sb + OFF_BHI + soff1, h0, h1); STS64(sb + OFF_BLO + soff1, l0, l1);
    }
    __syncthreads();

    #pragma unroll 1
    for (int kt = 0; kt < NK; kt++) {
        uint32_t cur = sb + (uint32_t)((kt & 1) * BUF_SZ);
        // issue next-tile LDGs early
        if (kt + 1 < NK) {
            int ko = (kt + 1) * 16;
            pa0 = aptr0 ? *(const float4*)(aptr0 + ko) : Z;
            pa1 = aptr1 ? *(const float4*)(aptr1 + ko) : Z;
            pb0 = *(const float4*)(bptr0 + ko);
            pb1 = *(const float4*)(bptr1 + ko);
        }

        // -------- compute one k=16 slab (warp tile 64x32, 2-term fp16)
        {
            uint32_t aH[4][4];
            #pragma unroll
            for (int mt = 0; mt < 4; mt++) {
                int row = wm * 64 + mt * 16 + (lane & 15);
                uint32_t ad = swz16(row, lane >> 4);
                ldsm_x4(aH[mt], cur + ad);
            }
            #pragma unroll
            for (int np = 0; np < 2; np++) {
                int row = wn * 32 + np * 16 + (lane & 7) + ((lane >> 4) << 3);
                uint32_t bd = swz16(row, (lane >> 3) & 1);
                uint32_t tH[4], tL[4];
                ldsm_x4(tH, cur + OFF_BHI + bd);
                ldsm_x4(tL, cur + OFF_BLO + bd);
                uint32_t bH0[2] = {tH[0], tH[1]}, bH1[2] = {tH[2], tH[3]};
                uint32_t bL0[2] = {tL[0], tL[1]}, bL1[2] = {tL[2], tL[3]};
                #pragma unroll
                for (int mt = 0; mt < 4; mt++) {
                    mma16816(acc[mt][2*np],   aH[mt], bH0);
                    mma16816(acc[mt][2*np+1], aH[mt], bH1);
                }
                #pragma unroll
                for (int mt = 0; mt < 4; mt++) {
                    mma16816(acc[mt][2*np],   aH[mt], bL0);
                    mma16816(acc[mt][2*np+1], aH[mt], bL1);
                }
            }
        }

        // stage next slab into the other buffer
        if (kt + 1 < NK) {
            uint32_t nxt = sb + (uint32_t)(((kt + 1) & 1) * BUF_SZ);
            uint32_t h0, h1, l0, l1;
            cvt4h(pa0, h0, h1);          STS64(nxt + soff0, h0, h1);
            cvt4h(pa1, h0, h1);          STS64(nxt + soff1, h0, h1);
            cvt4hs(pb0, h0, h1, l0, l1); STS64(nxt + OFF_BHI + soff0, h0, h1); STS64(nxt + OFF_BLO + soff0, l0, l1);
            cvt4hs(pb1, h0, h1, l0, l1); STS64(nxt + OFF_BHI + soff1, h0, h1); STS64(nxt + OFF_BLO + soff1, l0, l1);
        }
        __syncthreads();
    }

    if (FUSED) {
        float* sUp = (float*)smem;   // [128][64] f32 = 32KB (fits dynamic smem exactly)
        if (wn >= 2) {
            #pragma unroll
            for (int mt = 0; mt < 4; mt++)
                #pragma unroll
                for (int nt = 0; nt < 4; nt++) {
                    int m = wm * 64 + mt * 16 + (lane >> 2);
                    int c = (wn - 2) * 32 + nt * 8 + (lane & 3) * 2;
                    sUp[m * 64 + c]           = acc[mt][nt][0];
                    sUp[m * 64 + c + 1]       = acc[mt][nt][1];
                    sUp[(m + 8) * 64 + c]     = acc[mt][nt][2];
                    sUp[(m + 8) * 64 + c + 1] = acc[mt][nt][3];
                }
        }
        __syncthreads();
        if (wn < 2) {
            #pragma unroll
            for (int mt = 0; mt < 4; mt++)
                #pragma unroll
                for (int nt = 0; nt < 4; nt++) {
                    int m = wm * 64 + mt * 16 + (lane >> 2);
                    int c = wn * 32 + nt * 8 + (lane & 3) * 2;
                    #pragma unroll
                    for (int h = 0; h < 2; h++) {
                        int mm = m + h * 8;
                        float g0 = acc[mt][nt][h * 2], g1 = acc[mt][nt][h * 2 + 1];
                        float u0 = sUp[mm * 64 + c], u1 = sUp[mm * 64 + c + 1];
                        float2 o;
                        o.x = g0 / (1.f + expf(-g0)) * u0;
                        o.y = g1 / (1.f + expf(-g1)) * u1;
                        *(float2*)&g_inter[(size_t)(row0 + mm) * IDIM + nb * 64 + c] = o;
                    }
                }
        }
    } else {
        #pragma unroll
        for (int mt = 0; mt < 4; mt++)
            #pragma unroll
            for (int nt = 0; nt < 4; nt++) {
                int m = row0 + wm * 64 + mt * 16 + (lane >> 2);
                int c = nb * 128 + wn * 32 + nt * 8 + (lane & 3) * 2;
                *(float2*)&g_y2[(size_t)m * HID + c]       = make_float2(acc[mt][nt][0], acc[mt][nt][1]);
                *(float2*)&g_y2[(size_t)(m + 8) * HID + c] = make_float2(acc[mt][nt][2], acc[mt][nt][3]);
            }
    }
}

// ---------------- combine ----------------
__global__ void combine_kernel(float* __restrict__ out) {
    __shared__ float w[TOPK];
    __shared__ int rows[TOPK];
    int t = blockIdx.x;
    int tid = threadIdx.x;
    if (tid < TOPK) {
        w[tid]    = g_topkw[t * TOPK + tid];
        rows[tid] = g_invperm[t * TOPK + tid];
    }
    __syncthreads();
    float4 acc = make_float4(0.f, 0.f, 0.f, 0.f);
    #pragma unroll
    for (int k = 0; k < TOPK; k++) {
        const float4 v = *(const float4*)&g_y2[(size_t)rows[k] * HID + (tid << 2)];
        float wk = w[k];
        acc.x += wk * v.x; acc.y += wk * v.y; acc.z += wk * v.z; acc.w += wk * v.w;
    }
    *(float4*)(out + (size_t)t * HID + (tid << 2)) = acc;
}

// ---------------- launch ----------------
extern "C" void kernel_launch(void* const* d_in, const int* in_sizes, int n_in,
                              void* d_out, int out_size) {
    const float* x    = (const float*)d_in[0];
    const float* gate = (const float*)d_in[1];
    const float* gup  = (const float*)d_in[2];
    const float* dwn  = (const float*)d_in[3];
    float* out = (float*)d_out;

    cudaFuncSetAttribute(moe_gemm<true>,  cudaFuncAttributeMaxDynamicSharedMemorySize, SMEM_BYTES);
    cudaFuncSetAttribute(moe_gemm<false>, cudaFuncAttributeMaxDynamicSharedMemorySize, SMEM_BYTES);

    initfill_kernel<<<(MPAD + 255) / 256, 256>>>();                     // launch 0
    router_kernel<<<NTOK / RT, 256>>>(x, gate);                         // launch 1
    metascatter_kernel<<<1, 256>>>();                                   // launch 2
    moe_gemm<true><<<dim3(MAXTILES, IDIM / 64), 256, SMEM_BYTES>>>(x, gup);        // launch 3 (profiled)
    moe_gemm<false><<<dim3(MAXTILES, HID / 128), 256, SMEM_BYTES>>>(nullptr, dwn); // launch 4
    combine_kernel<<<NTOK, 256>>>(out);                                 // launch 5
}

// round 14
// speedup vs baseline: 1.5407x; 1.0943x over previous
#include <cuda_runtime.h>
#include <cuda_fp16.h>
#include <cstdint>

#define NTOK 4096
#define HID  1024
#define NEXP 64
#define TOPK 8
#define IDIM 768
#define FLAT (NTOK*TOPK)
#define BM   128
#define MPAD 40960
#define MAXTILES 320

// ---------------- scratch ----------------
static __device__ float g_inter[(size_t)MPAD * IDIM];
static __device__ float g_y2[(size_t)MPAD * HID];
static __device__ float g_topkw[FLAT];
static __device__ int   g_flatexp[FLAT];
static __device__ int   g_invperm[FLAT];
static __device__ int   g_rowtok[MPAD];
static __device__ int   g_counts[NEXP];
static __device__ int   g_ctr[NEXP];
static __device__ int   g_offpad[NEXP];
static __device__ int   g_tile_e[MAXTILES];
static __device__ int   g_tile_r0[MAXTILES];
static __device__ int   g_ntiles;

// ---------------- helpers ----------------
__device__ __forceinline__ uint32_t smem_u32(const void* p) {
    uint32_t a;
    asm("{ .reg .u64 t; cvta.to.shared.u64 t, %1; cvt.u32.u64 %0, t; }" : "=r"(a) : "l"(p));
    return a;
}
#define STS64(a, v0, v1) \
    asm volatile("st.shared.v2.b32 [%0], {%1, %2};" :: "r"(a), "r"(v0), "r"(v1) : "memory")

__device__ __forceinline__ void ldsm_x4(uint32_t (&r)[4], uint32_t addr) {
    asm volatile("ldmatrix.sync.aligned.m8n8.x4.shared.b16 {%0,%1,%2,%3}, [%4];"
        : "=r"(r[0]), "=r"(r[1]), "=r"(r[2]), "=r"(r[3]) : "r"(addr));
}
__device__ __forceinline__ void mma16816(float (&d)[4], const uint32_t (&a)[4], const uint32_t (&b)[2]) {
    asm volatile("mma.sync.aligned.m16n8k16.row.col.f32.f16.f16.f32 "
        "{%0,%1,%2,%3}, {%4,%5,%6,%7}, {%8,%9}, {%0,%1,%2,%3};"
        : "+f"(d[0]), "+f"(d[1]), "+f"(d[2]), "+f"(d[3])
        : "r"(a[0]), "r"(a[1]), "r"(a[2]), "r"(a[3]), "r"(b[0]), "r"(b[1]));
}

// 4 fp32 -> 4 fp16 packed (2x u32), single rounding
__device__ __forceinline__ void cvt4h(const float4 f, uint32_t& h0, uint32_t& h1) {
    __half2 h;
    h = __floats2half2_rn(f.x, f.y); h0 = *(uint32_t*)&h;
    h = __floats2half2_rn(f.z, f.w); h1 = *(uint32_t*)&h;
}

// swizzled byte offset within a [rows][16 fp16] tile (32B rows, 2x16B chunks)
__device__ __forceinline__ uint32_t swz16(int row, int ch) {
    return (uint32_t)(row * 32 + ((ch ^ ((row >> 2) & 1)) << 4));
}

// ---------------- small kernels (gemm1 stays the 4th launch for ncu) ----------------
__global__ void initfill_kernel() {
    int i = blockIdx.x * 256 + threadIdx.x;
    if (i < MPAD) g_rowtok[i] = -1;
    if (i < NEXP) { g_counts[i] = 0; g_ctr[i] = 0; }
}

#define RT 8
__global__ void router_kernel(const float* __restrict__ x, const float* __restrict__ gate) {
    __shared__ float xs[RT][HID];
    __shared__ float lg[RT][NEXP];
    int t0 = blockIdx.x * RT;
    int tid = threadIdx.x;  // 256
    const float4* xsrc = (const float4*)(x + (size_t)t0 * HID);
    for (int i = tid; i < RT * HID / 4; i += 256) ((float4*)&xs[0][0])[i] = xsrc[i];
    __syncthreads();
    int tt = tid >> 5, lane = tid & 31;
    #pragma unroll
    for (int g = 0; g < 2; g++) {
        int e = g * 32 + lane;
        const float* gp = gate + (size_t)e * HID;
        float s = 0.f;
        #pragma unroll 4
        for (int k = 0; k < HID; k += 4) {
            float4 gv = *(const float4*)(gp + k);
            s += xs[tt][k] * gv.x + xs[tt][k+1] * gv.y + xs[tt][k+2] * gv.z + xs[tt][k+3] * gv.w;
        }
        lg[tt][e] = s;
    }
    __syncthreads();
    if (tid < RT) {
        int t = t0 + tid;
        float mx = lg[tid][0];
        #pragma unroll
        for (int e = 1; e < NEXP; e++) mx = fmaxf(mx, lg[tid][e]);
        unsigned long long taken = 0ull;
        float wsum = 0.f;
        int sel[TOPK]; float wv[TOPK];
        for (int k = 0; k < TOPK; k++) {
            int best = 0; float bv = -1e30f;
            for (int e = 0; e < NEXP; e++) {
                float v = lg[tid][e];
                if (!((taken >> e) & 1ull) && v > bv) { bv = v; best = e; }
            }
            taken |= 1ull << best;
            sel[k] = best;
            float w = expf(lg[tid][best] - mx);
            wv[k] = w; wsum += w;
            atomicAdd(&g_counts[best], 1);
        }
        float inv = 1.f / wsum;
        for (int k = 0; k < TOPK; k++) {
            g_topkw[t * TOPK + k]   = wv[k] * inv;
            g_flatexp[t * TOPK + k] = sel[k];
        }
    }
}

__global__ void metascatter_kernel() {
    int tid = threadIdx.x;   // 256
    if (tid == 0) {
        int nt = 0, cum = 0;
        for (int e = 0; e < NEXP; e++) {
            g_offpad[e] = cum;
            int c = g_counts[e];
            int t = (c + BM - 1) / BM;
            for (int j = 0; j < t; j++) { g_tile_e[nt] = e; g_tile_r0[nt] = cum + j * BM; nt++; }
            cum += t * BM;
        }
        g_ntiles = nt;
    }
    __syncthreads();
    for (int i = tid; i < FLAT; i += 256) {
        int e = g_flatexp[i];
        int dest = g_offpad[e] + atomicAdd(&g_ctr[e], 1);
        g_rowtok[dest] = i >> 3;
        g_invperm[i] = dest;
    }
}

// ---------------- grouped GEMM: single fp16 both operands, KC=16, 2 CTA/SM ----------
// CTA: 256 thr = 8 warps (2x4), tile M=128 x N=128, warp tile 64x32.
// Copy mapping: 4 consecutive lanes cover one row's 64B (1 line-touch per row).
// Buffer = A(4K)|B(4K) = 8KB; double-buffered in first 16KB of 32KB dynamic smem
// (32KB needed for the FUSED epilogue exchange).
// D = A_f16 * B_f16 (single mma per acc per k-step)

#define BUF_SZ  8192
#define OFF_B   4096
#define SMEM_BYTES 32768

template<bool FUSED>
__global__ void __launch_bounds__(256, 2) moe_gemm(const float* __restrict__ Ain,
                                                   const float* __restrict__ W) {
    constexpr int KDIM = FUSED ? HID : IDIM;   // 1024 / 768
    constexpr int NK   = KDIM / 16;            // 64 / 48
    int tile = blockIdx.x;
    if (tile >= g_ntiles) return;
    int e = g_tile_e[tile], row0 = g_tile_r0[tile], nb = blockIdx.y;

    extern __shared__ __align__(128) char smem[];
    uint32_t sb = smem_u32(smem);

    int tid = threadIdx.x, lane = tid & 31, wid = tid >> 5;
    int wm = wid >> 2, wn = wid & 3;

    // -------- copy mapping: rows r0 = tid/4, r1 = 64 + tid/4; ch16 = tid&3 (16B units)
    int r0 = tid >> 2, r1 = r0 + 64, ch = tid & 3;
    uint32_t soff0 = swz16(r0, ch >> 1) + (uint32_t)((ch & 1) * 8);
    uint32_t soff1 = swz16(r1, ch >> 1) + (uint32_t)((ch & 1) * 8);

    const float* A = FUSED ? Ain : (const float*)g_inter;
    const float *aptr0, *aptr1;
    if (FUSED) {
        int t0 = g_rowtok[row0 + r0], t1 = g_rowtok[row0 + r1];
        aptr0 = (t0 >= 0) ? A + (size_t)t0 * HID + ch * 4 : nullptr;
        aptr1 = (t1 >= 0) ? A + (size_t)t1 * HID + ch * 4 : nullptr;
    } else {
        aptr0 = A + (size_t)(row0 + r0) * IDIM + ch * 4;
        aptr1 = A + (size_t)(row0 + r1) * IDIM + ch * 4;
    }
    const float* Wb = W + (size_t)e * (size_t)(FUSED ? 2 * IDIM : HID) * KDIM;
    int wr0 = FUSED ? (nb * 64 + r0) : (nb * 128 + r0);            // r0 in 0..63
    int wr1 = FUSED ? (IDIM + nb * 64 + (r1 - 64)) : (nb * 128 + r1);
    const float* bptr0 = Wb + (size_t)wr0 * KDIM + ch * 4;
    const float* bptr1 = Wb + (size_t)wr1 * KDIM + ch * 4;

    float acc[4][4][4];
    #pragma unroll
    for (int a = 0; a < 4; a++)
        #pragma unroll
        for (int b = 0; b < 4; b++)
            #pragma unroll
            for (int c = 0; c < 4; c++) acc[a][b][c] = 0.f;

    const float4 Z = make_float4(0.f, 0.f, 0.f, 0.f);
    float4 pa0, pa1, pb0, pb1;
    // prefetch kt = 0
    pa0 = aptr0 ? *(const float4*)(aptr0) : Z;
    pa1 = aptr1 ? *(const float4*)(aptr1) : Z;
    pb0 = *(const float4*)(bptr0);
    pb1 = *(const float4*)(bptr1);
    // fill buffer 0
    {
        uint32_t h0, h1;
        cvt4h(pa0, h0, h1); STS64(sb + soff0, h0, h1);
        cvt4h(pa1, h0, h1); STS64(sb + soff1, h0, h1);
        cvt4h(pb0, h0, h1); STS64(sb + OFF_B + soff0, h0, h1);
        cvt4h(pb1, h0, h1); STS64(sb + OFF_B + soff1, h0, h1);
    }
    __syncthreads();

    #pragma unroll 1
    for (int kt = 0; kt < NK; kt++) {
        uint32_t cur = sb + (uint32_t)((kt & 1) * BUF_SZ);
        // issue next-tile LDGs early
        if (kt + 1 < NK) {
            int ko = (kt + 1) * 16;
            pa0 = aptr0 ? *(const float4*)(aptr0 + ko) : Z;
            pa1 = aptr1 ? *(const float4*)(aptr1 + ko) : Z;
            pb0 = *(const float4*)(bptr0 + ko);
            pb1 = *(const float4*)(bptr1 + ko);
        }

        // -------- compute one k=16 slab (warp tile 64x32, single fp16)
        {
            uint32_t aH[4][4];
            #pragma unroll
            for (int mt = 0; mt < 4; mt++) {
                int row = wm * 64 + mt * 16 + (lane & 15);
                uint32_t ad = swz16(row, lane >> 4);
                ldsm_x4(aH[mt], cur + ad);
            }
            #pragma unroll
            for (int np = 0; np < 2; np++) {
                int row = wn * 32 + np * 16 + (lane & 7) + ((lane >> 4) << 3);
                uint32_t bd = swz16(row, (lane >> 3) & 1);
                uint32_t tH[4];
                ldsm_x4(tH, cur + OFF_B + bd);
                uint32_t bH0[2] = {tH[0], tH[1]}, bH1[2] = {tH[2], tH[3]};
                #pragma unroll
                for (int mt = 0; mt < 4; mt++) {
                    mma16816(acc[mt][2*np],   aH[mt], bH0);
                    mma16816(acc[mt][2*np+1], aH[mt], bH1);
                }
            }
        }

        // stage next slab into the other buffer
        if (kt + 1 < NK) {
            uint32_t nxt = sb + (uint32_t)(((kt + 1) & 1) * BUF_SZ);
            uint32_t h0, h1;
            cvt4h(pa0, h0, h1); STS64(nxt + soff0, h0, h1);
            cvt4h(pa1, h0, h1); STS64(nxt + soff1, h0, h1);
            cvt4h(pb0, h0, h1); STS64(nxt + OFF_B + soff0, h0, h1);
            cvt4h(pb1, h0, h1); STS64(nxt + OFF_B + soff1, h0, h1);
        }
        __syncthreads();
    }

    if (FUSED) {
        float* sUp = (float*)smem;   // [128][64] f32 = 32KB
        if (wn >= 2) {
            #pragma unroll
            for (int mt = 0; mt < 4; mt++)
                #pragma unroll
                for (int nt = 0; nt < 4; nt++) {
                    int m = wm * 64 + mt * 16 + (lane >> 2);
                    int c = (wn - 2) * 32 + nt * 8 + (lane & 3) * 2;
                    sUp[m * 64 + c]           = acc[mt][nt][0];
                    sUp[m * 64 + c + 1]       = acc[mt][nt][1];
                    sUp[(m + 8) * 64 + c]     = acc[mt][nt][2];
                    sUp[(m + 8) * 64 + c + 1] = acc[mt][nt][3];
                }
        }
        __syncthreads();
        if (wn < 2) {
            #pragma unroll
            for (int mt = 0; mt < 4; mt++)
                #pragma unroll
                for (int nt = 0; nt < 4; nt++) {
                    int m = wm * 64 + mt * 16 + (lane >> 2);
                    int c = wn * 32 + nt * 8 + (lane & 3) * 2;
                    #pragma unroll
                    for (int h = 0; h < 2; h++) {
                        int mm = m + h * 8;
                        float g0 = acc[mt][nt][h * 2], g1 = acc[mt][nt][h * 2 + 1];
                        float u0 = sUp[mm * 64 + c], u1 = sUp[mm * 64 + c + 1];
                        float2 o;
                        o.x = g0 / (1.f + expf(-g0)) * u0;
                        o.y = g1 / (1.f + expf(-g1)) * u1;
                        *(float2*)&g_inter[(size_t)(row0 + mm) * IDIM + nb * 64 + c] = o;
                    }
                }
        }
    } else {
        #pragma unroll
        for (int mt = 0; mt < 4; mt++)
            #pragma unroll
            for (int nt = 0; nt < 4; nt++) {
                int m = row0 + wm * 64 + mt * 16 + (lane >> 2);
                int c = nb * 128 + wn * 32 + nt * 8 + (lane & 3) * 2;
                *(float2*)&g_y2[(size_t)m * HID + c]       = make_float2(acc[mt][nt][0], acc[mt][nt][1]);
                *(float2*)&g_y2[(size_t)(m + 8) * HID + c] = make_float2(acc[mt][nt][2], acc[mt][nt][3]);
            }
    }
}

// ---------------- combine ----------------
__global__ void combine_kernel(float* __restrict__ out) {
    __shared__ float w[TOPK];
    __shared__ int rows[TOPK];
    int t = blockIdx.x;
    int tid = threadIdx.x;
    if (tid < TOPK) {
        w[tid]    = g_topkw[t * TOPK + tid];
        rows[tid] = g_invperm[t * TOPK + tid];
    }
    __syncthreads();
    float4 acc = make_float4(0.f, 0.f, 0.f, 0.f);
    #pragma unroll
    for (int k = 0; k < TOPK; k++) {
        const float4 v = *(const float4*)&g_y2[(size_t)rows[k] * HID + (tid << 2)];
        float wk = w[k];
        acc.x += wk * v.x; acc.y += wk * v.y; acc.z += wk * v.z; acc.w += wk * v.w;
    }
    *(float4*)(out + (size_t)t * HID + (tid << 2)) = acc;
}

// ---------------- launch ----------------
extern "C" void kernel_launch(void* const* d_in, const int* in_sizes, int n_in,
                              void* d_out, int out_size) {
    const float* x    = (const float*)d_in[0];
    const float* gate = (const float*)d_in[1];
    const float* gup  = (const float*)d_in[2];
    const float* dwn  = (const float*)d_in[3];
    float* out = (float*)d_out;

    cudaFuncSetAttribute(moe_gemm<true>,  cudaFuncAttributeMaxDynamicSharedMemorySize, SMEM_BYTES);
    cudaFuncSetAttribute(moe_gemm<false>, cudaFuncAttributeMaxDynamicSharedMemorySize, SMEM_BYTES);

    initfill_kernel<<<(MPAD + 255) / 256, 256>>>();                     // launch 0
    router_kernel<<<NTOK / RT, 256>>>(x, gate);                         // launch 1
    metascatter_kernel<<<1, 256>>>();                                   // launch 2
    moe_gemm<true><<<dim3(MAXTILES, IDIM / 64), 256, SMEM_BYTES>>>(x, gup);        // launch 3 (profiled)
    moe_gemm<false><<<dim3(MAXTILES, HID / 128), 256, SMEM_BYTES>>>(nullptr, dwn); // launch 4
    combine_kernel<<<NTOK, 256>>>(out);                                 // launch 5
}

// round 15
// speedup vs baseline: 1.5866x; 1.0298x over previous
#include <cuda_runtime.h>
#include <cuda_fp16.h>
#include <cstdint>

#define NTOK 4096
#define HID  1024
#define NEXP 64
#define TOPK 8
#define IDIM 768
#define FLAT (NTOK*TOPK)
#define BM   128
#define MPAD 40960
#define MAXTILES 320

// ---------------- scratch ----------------
static __device__ __half g_inter[(size_t)MPAD * IDIM];   // fp16 intermediate
static __device__ float g_y2[(size_t)MPAD * HID];
static __device__ float g_topkw[FLAT];
static __device__ int   g_flatexp[FLAT];
static __device__ int   g_invperm[FLAT];
static __device__ int   g_rowtok[MPAD];
static __device__ int   g_counts[NEXP];
static __device__ int   g_ctr[NEXP];
static __device__ int   g_offpad[NEXP];
static __device__ int   g_tile_e[MAXTILES];
static __device__ int   g_tile_r0[MAXTILES];
static __device__ int   g_ntiles;

// ---------------- helpers ----------------
__device__ __forceinline__ uint32_t smem_u32(const void* p) {
    uint32_t a;
    asm("{ .reg .u64 t; cvta.to.shared.u64 t, %1; cvt.u32.u64 %0, t; }" : "=r"(a) : "l"(p));
    return a;
}
#define STS64(a, v0, v1) \
    asm volatile("st.shared.v2.b32 [%0], {%1, %2};" :: "r"(a), "r"(v0), "r"(v1) : "memory")
#define STS128(a, v) \
    asm volatile("st.shared.v4.b32 [%0], {%1, %2, %3, %4};" \
        :: "r"(a), "r"((v).x), "r"((v).y), "r"((v).z), "r"((v).w) : "memory")

__device__ __forceinline__ void ldsm_x4(uint32_t (&r)[4], uint32_t addr) {
    asm volatile("ldmatrix.sync.aligned.m8n8.x4.shared.b16 {%0,%1,%2,%3}, [%4];"
        : "=r"(r[0]), "=r"(r[1]), "=r"(r[2]), "=r"(r[3]) : "r"(addr));
}
__device__ __forceinline__ void mma16816(float (&d)[4], const uint32_t (&a)[4], const uint32_t (&b)[2]) {
    asm volatile("mma.sync.aligned.m16n8k16.row.col.f32.f16.f16.f32 "
        "{%0,%1,%2,%3}, {%4,%5,%6,%7}, {%8,%9}, {%0,%1,%2,%3};"
        : "+f"(d[0]), "+f"(d[1]), "+f"(d[2]), "+f"(d[3])
        : "r"(a[0]), "r"(a[1]), "r"(a[2]), "r"(a[3]), "r"(b[0]), "r"(b[1]));
}

// 4 fp32 -> 4 fp16 packed (2x u32)
__device__ __forceinline__ void cvt4h(const float4 f, uint32_t& h0, uint32_t& h1) {
    __half2 h;
    h = __floats2half2_rn(f.x, f.y); h0 = *(uint32_t*)&h;
    h = __floats2half2_rn(f.z, f.w); h1 = *(uint32_t*)&h;
}

// swizzled byte offset within a [rows][16 fp16] tile (32B rows, 2x16B chunks)
__device__ __forceinline__ uint32_t swz16(int row, int ch) {
    return (uint32_t)(row * 32 + ((ch ^ ((row >> 2) & 1)) << 4));
}

// ---------------- small kernels (gemm1 stays the 4th launch for ncu) ----------------
__global__ void initfill_kernel() {
    int i = blockIdx.x * 256 + threadIdx.x;
    if (i < MPAD) g_rowtok[i] = -1;
    if (i < NEXP) { g_counts[i] = 0; g_ctr[i] = 0; }
}

#define RT 8
__global__ void router_kernel(const float* __restrict__ x, const float* __restrict__ gate) {
    __shared__ float xs[RT][HID];
    __shared__ float lg[RT][NEXP];
    int t0 = blockIdx.x * RT;
    int tid = threadIdx.x;  // 256
    const float4* xsrc = (const float4*)(x + (size_t)t0 * HID);
    for (int i = tid; i < RT * HID / 4; i += 256) ((float4*)&xs[0][0])[i] = xsrc[i];
    __syncthreads();
    int tt = tid >> 5, lane = tid & 31;
    #pragma unroll
    for (int g = 0; g < 2; g++) {
        int e = g * 32 + lane;
        const float* gp = gate + (size_t)e * HID;
        float s = 0.f;
        #pragma unroll 4
        for (int k = 0; k < HID; k += 4) {
            float4 gv = *(const float4*)(gp + k);
            s += xs[tt][k] * gv.x + xs[tt][k+1] * gv.y + xs[tt][k+2] * gv.z + xs[tt][k+3] * gv.w;
        }
        lg[tt][e] = s;
    }
    __syncthreads();
    if (tid < RT) {
        int t = t0 + tid;
        float mx = lg[tid][0];
        #pragma unroll
        for (int e = 1; e < NEXP; e++) mx = fmaxf(mx, lg[tid][e]);
        unsigned long long taken = 0ull;
        float wsum = 0.f;
        int sel[TOPK]; float wv[TOPK];
        for (int k = 0; k < TOPK; k++) {
            int best = 0; float bv = -1e30f;
            for (int e = 0; e < NEXP; e++) {
                float v = lg[tid][e];
                if (!((taken >> e) & 1ull) && v > bv) { bv = v; best = e; }
            }
            taken |= 1ull << best;
            sel[k] = best;
            float w = expf(lg[tid][best] - mx);
            wv[k] = w; wsum += w;
            atomicAdd(&g_counts[best], 1);
        }
        float inv = 1.f / wsum;
        for (int k = 0; k < TOPK; k++) {
            g_topkw[t * TOPK + k]   = wv[k] * inv;
            g_flatexp[t * TOPK + k] = sel[k];
        }
    }
}

__global__ void metascatter_kernel() {
    int tid = threadIdx.x;   // 256
    if (tid == 0) {
        int nt = 0, cum = 0;
        for (int e = 0; e < NEXP; e++) {
            g_offpad[e] = cum;
            int c = g_counts[e];
            int t = (c + BM - 1) / BM;
            for (int j = 0; j < t; j++) { g_tile_e[nt] = e; g_tile_r0[nt] = cum + j * BM; nt++; }
            cum += t * BM;
        }
        g_ntiles = nt;
    }
    __syncthreads();
    for (int i = tid; i < FLAT; i += 256) {
        int e = g_flatexp[i];
        int dest = g_offpad[e] + atomicAdd(&g_ctr[e], 1);
        g_rowtok[dest] = i >> 3;
        g_invperm[i] = dest;
    }
}

// ---------------- grouped GEMM: single fp16, KC=16, 2 CTA/SM, grid(nb, tile) ----------
// CTA: 256 thr = 8 warps (2x4), tile M=128 x N=128, warp tile 64x32.
// grid.x = nb, grid.y = tile: CTAs sharing an A tile are launch-adjacent -> A tile
// is DRAM-read ~once, L2-served for the other nb blocks (critical for gemm2 whose
// A (g_inter) is ~63MB).
// FUSED:  A = x (fp32 gather, 4 lanes/row copy + cvt), writes g_inter as fp16.
// !FUSED: A = g_inter (fp16, 2 lanes/row straight 16B copy, no cvt), writes g_y2.

#define BUF_SZ  8192
#define OFF_B   4096
#define SMEM_BYTES 32768

template<bool FUSED>
__global__ void __launch_bounds__(256, 2) moe_gemm(const float* __restrict__ Ain,
                                                   const float* __restrict__ W) {
    constexpr int KDIM = FUSED ? HID : IDIM;   // 1024 / 768
    constexpr int NK   = KDIM / 16;            // 64 / 48
    int nb   = blockIdx.x;
    int tile = blockIdx.y;
    if (tile >= g_ntiles) return;
    int e = g_tile_e[tile], row0 = g_tile_r0[tile];

    extern __shared__ __align__(128) char smem[];
    uint32_t sb = smem_u32(smem);

    int tid = threadIdx.x, lane = tid & 31, wid = tid >> 5;
    int wm = wid >> 2, wn = wid & 3;

    // -------- B copy mapping (also A for FUSED): rows r0/r1, ch16 = tid&3
    int r0 = tid >> 2, r1 = r0 + 64, ch = tid & 3;
    uint32_t soff0 = swz16(r0, ch >> 1) + (uint32_t)((ch & 1) * 8);
    uint32_t soff1 = swz16(r1, ch >> 1) + (uint32_t)((ch & 1) * 8);

    // -------- A fp16 copy mapping (!FUSED): row = tid/2, 16B chunk = tid&1
    int rh = tid >> 1, chh = tid & 1;
    uint32_t soffh = swz16(rh, chh);

    const float *aptr0 = nullptr, *aptr1 = nullptr;
    const __half* aptrh = nullptr;
    if (FUSED) {
        int t0 = g_rowtok[row0 + r0], t1 = g_rowtok[row0 + r1];
        aptr0 = (t0 >= 0) ? Ain + (size_t)t0 * HID + ch * 4 : nullptr;
        aptr1 = (t1 >= 0) ? Ain + (size_t)t1 * HID + ch * 4 : nullptr;
    } else {
        aptrh = g_inter + (size_t)(row0 + rh) * IDIM + chh * 8;
    }
    const float* Wb = W + (size_t)e * (size_t)(FUSED ? 2 * IDIM : HID) * KDIM;
    int wr0 = FUSED ? (nb * 64 + r0) : (nb * 128 + r0);            // r0 in 0..63
    int wr1 = FUSED ? (IDIM + nb * 64 + (r1 - 64)) : (nb * 128 + r1);
    const float* bptr0 = Wb + (size_t)wr0 * KDIM + ch * 4;
    const float* bptr1 = Wb + (size_t)wr1 * KDIM + ch * 4;

    float acc[4][4][4];
    #pragma unroll
    for (int a = 0; a < 4; a++)
        #pragma unroll
        for (int b = 0; b < 4; b++)
            #pragma unroll
            for (int c = 0; c < 4; c++) acc[a][b][c] = 0.f;

    const float4 Z = make_float4(0.f, 0.f, 0.f, 0.f);
    float4 pa0, pa1, pb0, pb1;
    uint4 pah;
    // prefetch kt = 0
    if (FUSED) {
        pa0 = aptr0 ? *(const float4*)(aptr0) : Z;
        pa1 = aptr1 ? *(const float4*)(aptr1) : Z;
    } else {
        pah = *(const uint4*)(aptrh);
    }
    pb0 = *(const float4*)(bptr0);
    pb1 = *(const float4*)(bptr1);
    // fill buffer 0
    {
        uint32_t h0, h1;
        if (FUSED) {
            cvt4h(pa0, h0, h1); STS64(sb + soff0, h0, h1);
            cvt4h(pa1, h0, h1); STS64(sb + soff1, h0, h1);
        } else {
            STS128(sb + soffh, pah);
        }
        cvt4h(pb0, h0, h1); STS64(sb + OFF_B + soff0, h0, h1);
        cvt4h(pb1, h0, h1); STS64(sb + OFF_B + soff1, h0, h1);
    }
    __syncthreads();

    #pragma unroll 1
    for (int kt = 0; kt < NK; kt++) {
        uint32_t cur = sb + (uint32_t)((kt & 1) * BUF_SZ);
        // issue next-tile LDGs early
        if (kt + 1 < NK) {
            int ko = (kt + 1) * 16;
            if (FUSED) {
                pa0 = aptr0 ? *(const float4*)(aptr0 + ko) : Z;
                pa1 = aptr1 ? *(const float4*)(aptr1 + ko) : Z;
            } else {
                pah = *(const uint4*)(aptrh + ko);
            }
            pb0 = *(const float4*)(bptr0 + ko);
            pb1 = *(const float4*)(bptr1 + ko);
        }

        // -------- compute one k=16 slab (warp tile 64x32, single fp16)
        {
            uint32_t aH[4][4];
            #pragma unroll
            for (int mt = 0; mt < 4; mt++) {
                int row = wm * 64 + mt * 16 + (lane & 15);
                uint32_t ad = swz16(row, lane >> 4);
                ldsm_x4(aH[mt], cur + ad);
            }
            #pragma unroll
            for (int np = 0; np < 2; np++) {
                int row = wn * 32 + np * 16 + (lane & 7) + ((lane >> 4) << 3);
                uint32_t bd = swz16(row, (lane >> 3) & 1);
                uint32_t tH[4];
                ldsm_x4(tH, cur + OFF_B + bd);
                uint32_t bH0[2] = {tH[0], tH[1]}, bH1[2] = {tH[2], tH[3]};
                #pragma unroll
                for (int mt = 0; mt < 4; mt++) {
                    mma16816(acc[mt][2*np],   aH[mt], bH0);
                    mma16816(acc[mt][2*np+1], aH[mt], bH1);
                }
            }
        }

        // stage next slab into the other buffer
        if (kt + 1 < NK) {
            uint32_t nxt = sb + (uint32_t)(((kt + 1) & 1) * BUF_SZ);
            uint32_t h0, h1;
            if (FUSED) {
                cvt4h(pa0, h0, h1); STS64(nxt + soff0, h0, h1);
                cvt4h(pa1, h0, h1); STS64(nxt + soff1, h0, h1);
            } else {
                STS128(nxt + soffh, pah);
            }
            cvt4h(pb0, h0, h1); STS64(nxt + OFF_B + soff0, h0, h1);
            cvt4h(pb1, h0, h1); STS64(nxt + OFF_B + soff1, h0, h1);
        }
        __syncthreads();
    }

    if (FUSED) {
        float* sUp = (float*)smem;   // [128][64] f32 = 32KB
        if (wn >= 2) {
            #pragma unroll
            for (int mt = 0; mt < 4; mt++)
                #pragma unroll
                for (int nt = 0; nt < 4; nt++) {
                    int m = wm * 64 + mt * 16 + (lane >> 2);
                    int c = (wn - 2) * 32 + nt * 8 + (lane & 3) * 2;
                    sUp[m * 64 + c]           = acc[mt][nt][0];
                    sUp[m * 64 + c + 1]       = acc[mt][nt][1];
                    sUp[(m + 8) * 64 + c]     = acc[mt][nt][2];
                    sUp[(m + 8) * 64 + c + 1] = acc[mt][nt][3];
                }
        }
        __syncthreads();
        if (wn < 2) {
            #pragma unroll
            for (int mt = 0; mt < 4; mt++)
                #pragma unroll
                for (int nt = 0; nt < 4; nt++) {
                    int m = wm * 64 + mt * 16 + (lane >> 2);
                    int c = wn * 32 + nt * 8 + (lane & 3) * 2;
                    #pragma unroll
                    for (int h = 0; h < 2; h++) {
                        int mm = m + h * 8;
                        float g0 = acc[mt][nt][h * 2], g1 = acc[mt][nt][h * 2 + 1];
                        float u0 = sUp[mm * 64 + c], u1 = sUp[mm * 64 + c + 1];
                        float o0 = g0 / (1.f + expf(-g0)) * u0;
                        float o1 = g1 / (1.f + expf(-g1)) * u1;
                        __half2 hp = __floats2half2_rn(o0, o1);
                        *(uint32_t*)&g_inter[(size_t)(row0 + mm) * IDIM + nb * 64 + c] = *(uint32_t*)&hp;
                    }
                }
        }
    } else {
        #pragma unroll
        for (int mt = 0; mt < 4; mt++)
            #pragma unroll
            for (int nt = 0; nt < 4; nt++) {
                int m = row0 + wm * 64 + mt * 16 + (lane >> 2);
                int c = nb * 128 + wn * 32 + nt * 8 + (lane & 3) * 2;
                *(float2*)&g_y2[(size_t)m * HID + c]       = make_float2(acc[mt][nt][0], acc[mt][nt][1]);
                *(float2*)&g_y2[(size_t)(m + 8) * HID + c] = make_float2(acc[mt][nt][2], acc[mt][nt][3]);
            }
    }
}

// ---------------- combine ----------------
__global__ void combine_kernel(float* __restrict__ out) {
    __shared__ float w[TOPK];
    __shared__ int rows[TOPK];
    int t = blockIdx.x;
    int tid = threadIdx.x;
    if (tid < TOPK) {
        w[tid]    = g_topkw[t * TOPK + tid];
        rows[tid] = g_invperm[t * TOPK + tid];
    }
    __syncthreads();
    float4 acc = make_float4(0.f, 0.f, 0.f, 0.f);
    #pragma unroll
    for (int k = 0; k < TOPK; k++) {
        const float4 v = *(const float4*)&g_y2[(size_t)rows[k] * HID + (tid << 2)];
        float wk = w[k];
        acc.x += wk * v.x; acc.y += wk * v.y; acc.z += wk * v.z; acc.w += wk * v.w;
    }
    *(float4*)(out + (size_t)t * HID + (tid << 2)) = acc;
}

// ---------------- launch ----------------
extern "C" void kernel_launch(void* const* d_in, const int* in_sizes, int n_in,
                              void* d_out, int out_size) {
    const float* x    = (const float*)d_in[0];
    const float* gate = (const float*)d_in[1];
    const float* gup  = (const float*)d_in[2];
    const float* dwn  = (const float*)d_in[3];
    float* out = (float*)d_out;

    cudaFuncSetAttribute(moe_gemm<true>,  cudaFuncAttributeMaxDynamicSharedMemorySize, SMEM_BYTES);
    cudaFuncSetAttribute(moe_gemm<false>, cudaFuncAttributeMaxDynamicSharedMemorySize, SMEM_BYTES);

    initfill_kernel<<<(MPAD + 255) / 256, 256>>>();                     // launch 0
    router_kernel<<<NTOK / RT, 256>>>(x, gate);                         // launch 1
    metascatter_kernel<<<1, 256>>>();                                   // launch 2
    moe_gemm<true><<<dim3(IDIM / 64, MAXTILES), 256, SMEM_BYTES>>>(x, gup);        // launch 3 (profiled)
    moe_gemm<false><<<dim3(HID / 128, MAXTILES), 256, SMEM_BYTES>>>(nullptr, dwn); // launch 4
    combine_kernel<<<NTOK, 256>>>(out);                                 // launch 5
}

// round 16
// speedup vs baseline: 1.6668x; 1.0506x over previous
#include <cuda_runtime.h>
#include <cuda_fp16.h>
#include <cstdint>

#define NTOK 4096
#define HID  1024
#define NEXP 64
#define TOPK 8
#define IDIM 768
#define FLAT (NTOK*TOPK)
#define BM   128
#define MPAD 40960
#define MAXTILES 320

// ---------------- scratch ----------------
static __device__ __half g_inter[(size_t)MPAD * IDIM];   // fp16 intermediate
static __device__ __half g_y2[(size_t)MPAD * HID];       // fp16 gemm2 output
static __device__ float g_topkw[FLAT];
static __device__ int   g_flatexp[FLAT];
static __device__ int   g_invperm[FLAT];
static __device__ int   g_rowtok[MPAD];
static __device__ int   g_tile_e[MAXTILES];
static __device__ int   g_tile_r0[MAXTILES];
static __device__ int   g_ntiles;

// ---------------- helpers ----------------
__device__ __forceinline__ uint32_t smem_u32(const void* p) {
    uint32_t a;
    asm("{ .reg .u64 t; cvta.to.shared.u64 t, %1; cvt.u32.u64 %0, t; }" : "=r"(a) : "l"(p));
    return a;
}
#define STS64(a, v0, v1) \
    asm volatile("st.shared.v2.b32 [%0], {%1, %2};" :: "r"(a), "r"(v0), "r"(v1) : "memory")
#define STS128(a, v) \
    asm volatile("st.shared.v4.b32 [%0], {%1, %2, %3, %4};" \
        :: "r"(a), "r"((v).x), "r"((v).y), "r"((v).z), "r"((v).w) : "memory")

__device__ __forceinline__ void ldsm_x4(uint32_t (&r)[4], uint32_t addr) {
    asm volatile("ldmatrix.sync.aligned.m8n8.x4.shared.b16 {%0,%1,%2,%3}, [%4];"
        : "=r"(r[0]), "=r"(r[1]), "=r"(r[2]), "=r"(r[3]) : "r"(addr));
}
__device__ __forceinline__ void mma16816(float (&d)[4], const uint32_t (&a)[4], const uint32_t (&b)[2]) {
    asm volatile("mma.sync.aligned.m16n8k16.row.col.f32.f16.f16.f32 "
        "{%0,%1,%2,%3}, {%4,%5,%6,%7}, {%8,%9}, {%0,%1,%2,%3};"
        : "+f"(d[0]), "+f"(d[1]), "+f"(d[2]), "+f"(d[3])
        : "r"(a[0]), "r"(a[1]), "r"(a[2]), "r"(a[3]), "r"(b[0]), "r"(b[1]));
}

// 4 fp32 -> 4 fp16 packed (2x u32)
__device__ __forceinline__ void cvt4h(const float4 f, uint32_t& h0, uint32_t& h1) {
    __half2 h;
    h = __floats2half2_rn(f.x, f.y); h0 = *(uint32_t*)&h;
    h = __floats2half2_rn(f.z, f.w); h1 = *(uint32_t*)&h;
}

// swizzled byte offset within a [rows][16 fp16] tile (32B rows, 2x16B chunks)
__device__ __forceinline__ uint32_t swz16(int row, int ch) {
    return (uint32_t)(row * 32 + ((ch ^ ((row >> 2) & 1)) << 4));
}

// ---------------- router (no count atomics; counts done in metascatter) ----------------
#define RT 8
__global__ void router_kernel(const float* __restrict__ x, const float* __restrict__ gate) {
    __shared__ float xs[RT][HID];
    __shared__ float lg[RT][NEXP];
    int t0 = blockIdx.x * RT;
    int tid = threadIdx.x;  // 256
    const float4* xsrc = (const float4*)(x + (size_t)t0 * HID);
    for (int i = tid; i < RT * HID / 4; i += 256) ((float4*)&xs[0][0])[i] = xsrc[i];
    __syncthreads();
    int tt = tid >> 5, lane = tid & 31;
    #pragma unroll
    for (int g = 0; g < 2; g++) {
        int e = g * 32 + lane;
        const float* gp = gate + (size_t)e * HID;
        float s = 0.f;
        #pragma unroll 4
        for (int k = 0; k < HID; k += 4) {
            float4 gv = *(const float4*)(gp + k);
            s += xs[tt][k] * gv.x + xs[tt][k+1] * gv.y + xs[tt][k+2] * gv.z + xs[tt][k+3] * gv.w;
        }
        lg[tt][e] = s;
    }
    __syncthreads();
    if (tid < RT) {
        int t = t0 + tid;
        float mx = lg[tid][0];
        #pragma unroll
        for (int e = 1; e < NEXP; e++) mx = fmaxf(mx, lg[tid][e]);
        unsigned long long taken = 0ull;
        float wsum = 0.f;
        int sel[TOPK]; float wv[TOPK];
        for (int k = 0; k < TOPK; k++) {
            int best = 0; float bv = -1e30f;
            for (int e = 0; e < NEXP; e++) {
                float v = lg[tid][e];
                if (!((taken >> e) & 1ull) && v > bv) { bv = v; best = e; }
            }
            taken |= 1ull << best;
            sel[k] = best;
            float w = expf(lg[tid][best] - mx);
            wv[k] = w; wsum += w;
        }
        float inv = 1.f / wsum;
        for (int k = 0; k < TOPK; k++) {
            g_topkw[t * TOPK + k]   = wv[k] * inv;
            g_flatexp[t * TOPK + k] = sel[k];
        }
    }
}

// ---------------- metascatter: fill + bincount + meta + scatter, one block ----------------
__global__ void metascatter_kernel() {
    __shared__ int scnt[NEXP];
    __shared__ int sctr[NEXP];
    __shared__ int soff[NEXP];
    int tid = threadIdx.x;   // 256
    if (tid < NEXP) { scnt[tid] = 0; sctr[tid] = 0; }
    for (int i = tid; i < MPAD; i += 256) g_rowtok[i] = -1;
    __syncthreads();
    for (int i = tid; i < FLAT; i += 256) atomicAdd(&scnt[g_flatexp[i]], 1);
    __syncthreads();
    if (tid == 0) {
        int nt = 0, cum = 0;
        for (int e = 0; e < NEXP; e++) {
            soff[e] = cum;
            int c = scnt[e];
            int t = (c + BM - 1) / BM;
            for (int j = 0; j < t; j++) { g_tile_e[nt] = e; g_tile_r0[nt] = cum + j * BM; nt++; }
            cum += t * BM;
        }
        g_ntiles = nt;
    }
    __syncthreads();
    for (int i = tid; i < FLAT; i += 256) {
        int e = g_flatexp[i];
        int dest = soff[e] + atomicAdd(&sctr[e], 1);
        g_rowtok[dest] = i >> 3;
        g_invperm[i] = dest;
    }
}

// ---------------- grouped GEMM: single fp16, KC=16, 2 CTA/SM, grid(nb, tile) ----------
// CTA: 256 thr = 8 warps (2x4), tile M=128 x N=128, warp tile 64x32.
// FUSED:  A = x (fp32 gather + cvt), writes g_inter fp16.
// !FUSED: A = g_inter (fp16 straight copy), writes g_y2 fp16.

#define BUF_SZ  8192
#define OFF_B   4096
#define SMEM_BYTES 32768

template<bool FUSED>
__global__ void __launch_bounds__(256, 2) moe_gemm(const float* __restrict__ Ain,
                                                   const float* __restrict__ W) {
    constexpr int KDIM = FUSED ? HID : IDIM;   // 1024 / 768
    constexpr int NK   = KDIM / 16;            // 64 / 48
    int nb   = blockIdx.x;
    int tile = blockIdx.y;
    if (tile >= g_ntiles) return;
    int e = g_tile_e[tile], row0 = g_tile_r0[tile];

    extern __shared__ __align__(128) char smem[];
    uint32_t sb = smem_u32(smem);

    int tid = threadIdx.x, lane = tid & 31, wid = tid >> 5;
    int wm = wid >> 2, wn = wid & 3;

    // -------- B copy mapping (also A for FUSED): rows r0/r1, ch16 = tid&3
    int r0 = tid >> 2, r1 = r0 + 64, ch = tid & 3;
    uint32_t soff0 = swz16(r0, ch >> 1) + (uint32_t)((ch & 1) * 8);
    uint32_t soff1 = swz16(r1, ch >> 1) + (uint32_t)((ch & 1) * 8);

    // -------- A fp16 copy mapping (!FUSED): row = tid/2, 16B chunk = tid&1
    int rh = tid >> 1, chh = tid & 1;
    uint32_t soffh = swz16(rh, chh);

    const float *aptr0 = nullptr, *aptr1 = nullptr;
    const __half* aptrh = nullptr;
    if (FUSED) {
        int t0 = g_rowtok[row0 + r0], t1 = g_rowtok[row0 + r1];
        aptr0 = (t0 >= 0) ? Ain + (size_t)t0 * HID + ch * 4 : nullptr;
        aptr1 = (t1 >= 0) ? Ain + (size_t)t1 * HID + ch * 4 : nullptr;
    } else {
        aptrh = g_inter + (size_t)(row0 + rh) * IDIM + chh * 8;
    }
    const float* Wb = W + (size_t)e * (size_t)(FUSED ? 2 * IDIM : HID) * KDIM;
    int wr0 = FUSED ? (nb * 64 + r0) : (nb * 128 + r0);            // r0 in 0..63
    int wr1 = FUSED ? (IDIM + nb * 64 + (r1 - 64)) : (nb * 128 + r1);
    const float* bptr0 = Wb + (size_t)wr0 * KDIM + ch * 4;
    const float* bptr1 = Wb + (size_t)wr1 * KDIM + ch * 4;

    float acc[4][4][4];
    #pragma unroll
    for (int a = 0; a < 4; a++)
        #pragma unroll
        for (int b = 0; b < 4; b++)
            #pragma unroll
            for (int c = 0; c < 4; c++) acc[a][b][c] = 0.f;

    const float4 Z = make_float4(0.f, 0.f, 0.f, 0.f);
    float4 pa0, pa1, pb0, pb1;
    uint4 pah;
    // prefetch kt = 0
    if (FUSED) {
        pa0 = aptr0 ? *(const float4*)(aptr0) : Z;
        pa1 = aptr1 ? *(const float4*)(aptr1) : Z;
    } else {
        pah = *(const uint4*)(aptrh);
    }
    pb0 = *(const float4*)(bptr0);
    pb1 = *(const float4*)(bptr1);
    // fill buffer 0
    {
        uint32_t h0, h1;
        if (FUSED) {
            cvt4h(pa0, h0, h1); STS64(sb + soff0, h0, h1);
            cvt4h(pa1, h0, h1); STS64(sb + soff1, h0, h1);
        } else {
            STS128(sb + soffh, pah);
        }
        cvt4h(pb0, h0, h1); STS64(sb + OFF_B + soff0, h0, h1);
        cvt4h(pb1, h0, h1); STS64(sb + OFF_B + soff1, h0, h1);
    }
    __syncthreads();

    #pragma unroll 1
    for (int kt = 0; kt < NK; kt++) {
        uint32_t cur = sb + (uint32_t)((kt & 1) * BUF_SZ);
        // issue next-tile LDGs early
        if (kt + 1 < NK) {
            int ko = (kt + 1) * 16;
            if (FUSED) {
                pa0 = aptr0 ? *(const float4*)(aptr0 + ko) : Z;
                pa1 = aptr1 ? *(const float4*)(aptr1 + ko) : Z;
            } else {
                pah = *(const uint4*)(aptrh + ko);
            }
            pb0 = *(const float4*)(bptr0 + ko);
            pb1 = *(const float4*)(bptr1 + ko);
        }

        // -------- compute one k=16 slab (warp tile 64x32, single fp16)
        {
            uint32_t aH[4][4];
            #pragma unroll
            for (int mt = 0; mt < 4; mt++) {
                int row = wm * 64 + mt * 16 + (lane & 15);
                uint32_t ad = swz16(row, lane >> 4);
                ldsm_x4(aH[mt], cur + ad);
            }
            #pragma unroll
            for (int np = 0; np < 2; np++) {
                int row = wn * 32 + np * 16 + (lane & 7) + ((lane >> 4) << 3);
                uint32_t bd = swz16(row, (lane >> 3) & 1);
                uint32_t tH[4];
                ldsm_x4(tH, cur + OFF_B + bd);
                uint32_t bH0[2] = {tH[0], tH[1]}, bH1[2] = {tH[2], tH[3]};
                #pragma unroll
                for (int mt = 0; mt < 4; mt++) {
                    mma16816(acc[mt][2*np],   aH[mt], bH0);
                    mma16816(acc[mt][2*np+1], aH[mt], bH1);
                }
            }
        }

        // stage next slab into the other buffer
        if (kt + 1 < NK) {
            uint32_t nxt = sb + (uint32_t)(((kt + 1) & 1) * BUF_SZ);
            uint32_t h0, h1;
            if (FUSED) {
                cvt4h(pa0, h0, h1); STS64(nxt + soff0, h0, h1);
                cvt4h(pa1, h0, h1); STS64(nxt + soff1, h0, h1);
            } else {
                STS128(nxt + soffh, pah);
            }
            cvt4h(pb0, h0, h1); STS64(nxt + OFF_B + soff0, h0, h1);
            cvt4h(pb1, h0, h1); STS64(nxt + OFF_B + soff1, h0, h1);
        }
        __syncthreads();
    }

    if (FUSED) {
        float* sUp = (float*)smem;   // [128][64] f32 = 32KB
        if (wn >= 2) {
            #pragma unroll
            for (int mt = 0; mt < 4; mt++)
                #pragma unroll
                for (int nt = 0; nt < 4; nt++) {
                    int m = wm * 64 + mt * 16 + (lane >> 2);
                    int c = (wn - 2) * 32 + nt * 8 + (lane & 3) * 2;
                    sUp[m * 64 + c]           = acc[mt][nt][0];
                    sUp[m * 64 + c + 1]       = acc[mt][nt][1];
                    sUp[(m + 8) * 64 + c]     = acc[mt][nt][2];
                    sUp[(m + 8) * 64 + c + 1] = acc[mt][nt][3];
                }
        }
        __syncthreads();
        if (wn < 2) {
            #pragma unroll
            for (int mt = 0; mt < 4; mt++)
                #pragma unroll
                for (int nt = 0; nt < 4; nt++) {
                    int m = wm * 64 + mt * 16 + (lane >> 2);
                    int c = wn * 32 + nt * 8 + (lane & 3) * 2;
                    #pragma unroll
                    for (int h = 0; h < 2; h++) {
                        int mm = m + h * 8;
                        float g0 = acc[mt][nt][h * 2], g1 = acc[mt][nt][h * 2 + 1];
                        float u0 = sUp[mm * 64 + c], u1 = sUp[mm * 64 + c + 1];
                        float o0 = g0 / (1.f + expf(-g0)) * u0;
                        float o1 = g1 / (1.f + expf(-g1)) * u1;
                        __half2 hp = __floats2half2_rn(o0, o1);
                        *(uint32_t*)&g_inter[(size_t)(row0 + mm) * IDIM + nb * 64 + c] = *(uint32_t*)&hp;
                    }
                }
        }
    } else {
        #pragma unroll
        for (int mt = 0; mt < 4; mt++)
            #pragma unroll
            for (int nt = 0; nt < 4; nt++) {
                int m = row0 + wm * 64 + mt * 16 + (lane >> 2);
                int c = nb * 128 + wn * 32 + nt * 8 + (lane & 3) * 2;
                __half2 h0 = __floats2half2_rn(acc[mt][nt][0], acc[mt][nt][1]);
                __half2 h1 = __floats2half2_rn(acc[mt][nt][2], acc[mt][nt][3]);
                *(uint32_t*)&g_y2[(size_t)m * HID + c]       = *(uint32_t*)&h0;
                *(uint32_t*)&g_y2[(size_t)(m + 8) * HID + c] = *(uint32_t*)&h1;
            }
    }
}

// ---------------- combine (y2 fp16) ----------------
__global__ void combine_kernel(float* __restrict__ out) {
    __shared__ float w[TOPK];
    __shared__ int rows[TOPK];
    int t = blockIdx.x;
    int tid = threadIdx.x;   // 256, 4 cols each
    if (tid < TOPK) {
        w[tid]    = g_topkw[t * TOPK + tid];
        rows[tid] = g_invperm[t * TOPK + tid];
    }
    __syncthreads();
    float4 acc = make_float4(0.f, 0.f, 0.f, 0.f);
    #pragma unroll
    for (int k = 0; k < TOPK; k++) {
        uint2 v = *(const uint2*)&g_y2[(size_t)rows[k] * HID + (tid << 2)];
        __half2 a = *(__half2*)&v.x;
        __half2 b = *(__half2*)&v.y;
        float2 fa = __half22float2(a), fb = __half22float2(b);
        float wk = w[k];
        acc.x += wk * fa.x; acc.y += wk * fa.y; acc.z += wk * fb.x; acc.w += wk * fb.y;
    }
    *(float4*)(out + (size_t)t * HID + (tid << 2)) = acc;
}

// ---------------- launch ----------------
extern "C" void kernel_launch(void* const* d_in, const int* in_sizes, int n_in,
                              void* d_out, int out_size) {
    const float* x    = (const float*)d_in[0];
    const float* gate = (const float*)d_in[1];
    const float* gup  = (const float*)d_in[2];
    const float* dwn  = (const float*)d_in[3];
    float* out = (float*)d_out;

    cudaFuncSetAttribute(moe_gemm<true>,  cudaFuncAttributeMaxDynamicSharedMemorySize, SMEM_BYTES);
    cudaFuncSetAttribute(moe_gemm<false>, cudaFuncAttributeMaxDynamicSharedMemorySize, SMEM_BYTES);

    router_kernel<<<NTOK / RT, 256>>>(x, gate);                                    // launch 0
    metascatter_kernel<<<1, 256>>>();                                              // launch 1
    moe_gemm<true><<<dim3(IDIM / 64, MAXTILES), 256, SMEM_BYTES>>>(x, gup);        // launch 2
    moe_gemm<false><<<dim3(HID / 128, MAXTILES), 256, SMEM_BYTES>>>(nullptr, dwn); // launch 3 (profiled)
    combine_kernel<<<NTOK, 256>>>(out);                                            // launch 4
}

// round 17
// speedup vs baseline: 1.6972x; 1.0182x over previous
#include <cuda_runtime.h>
#include <cuda_fp16.h>
#include <cstdint>

#define NTOK 4096
#define HID  1024
#define NEXP 64
#define TOPK 8
#define IDIM 768
#define FLAT (NTOK*TOPK)
#define BM   128
#define MPAD 40960
#define MAXTILES 320

// ---------------- scratch (zero-initialized at module load; combine re-zeros per run) ----
static __device__ __half g_xh[(size_t)NTOK * HID];       // fp16 tokens
static __device__ __half g_inter[(size_t)MPAD * IDIM];   // fp16 intermediate
static __device__ __half g_y2[(size_t)MPAD * HID];       // fp16 gemm2 output
static __device__ float g_topkw[FLAT];
static __device__ int   g_flatexp[FLAT];
static __device__ int   g_invperm[FLAT];
static __device__ int   g_rowtok[MPAD];                  // must be -1-filled; see note
static __device__ int   g_counts[NEXP];
static __device__ int   g_ctr[NEXP];
static __device__ int   g_offpad[NEXP];
static __device__ int   g_tile_e[MAXTILES];
static __device__ int   g_tile_r0[MAXTILES];
static __device__ int   g_ntiles;
static __device__ int   g_first = 0;   // 0 at load: rowtok needs initial fill in meta

// ---------------- helpers ----------------
__device__ __forceinline__ uint32_t smem_u32(const void* p) {
    uint32_t a;
    asm("{ .reg .u64 t; cvta.to.shared.u64 t, %1; cvt.u32.u64 %0, t; }" : "=r"(a) : "l"(p));
    return a;
}
#define STS64(a, v0, v1) \
    asm volatile("st.shared.v2.b32 [%0], {%1, %2};" :: "r"(a), "r"(v0), "r"(v1) : "memory")
#define STS128(a, v) \
    asm volatile("st.shared.v4.b32 [%0], {%1, %2, %3, %4};" \
        :: "r"(a), "r"((v).x), "r"((v).y), "r"((v).z), "r"((v).w) : "memory")

__device__ __forceinline__ void ldsm_x4(uint32_t (&r)[4], uint32_t addr) {
    asm volatile("ldmatrix.sync.aligned.m8n8.x4.shared.b16 {%0,%1,%2,%3}, [%4];"
        : "=r"(r[0]), "=r"(r[1]), "=r"(r[2]), "=r"(r[3]) : "r"(addr));
}
__device__ __forceinline__ void mma16816(float (&d)[4], const uint32_t (&a)[4], const uint32_t (&b)[2]) {
    asm volatile("mma.sync.aligned.m16n8k16.row.col.f32.f16.f16.f32 "
        "{%0,%1,%2,%3}, {%4,%5,%6,%7}, {%8,%9}, {%0,%1,%2,%3};"
        : "+f"(d[0]), "+f"(d[1]), "+f"(d[2]), "+f"(d[3])
        : "r"(a[0]), "r"(a[1]), "r"(a[2]), "r"(a[3]), "r"(b[0]), "r"(b[1]));
}

// 4 fp32 -> 4 fp16 packed (2x u32)
__device__ __forceinline__ void cvt4h(const float4 f, uint32_t& h0, uint32_t& h1) {
    __half2 h;
    h = __floats2half2_rn(f.x, f.y); h0 = *(uint32_t*)&h;
    h = __floats2half2_rn(f.z, f.w); h1 = *(uint32_t*)&h;
}

// swizzled byte offset within a [rows][16 fp16] tile (32B rows, 2x16B chunks)
__device__ __forceinline__ uint32_t swz16(int row, int ch) {
    return (uint32_t)(row * 32 + ((ch ^ ((row >> 2) & 1)) << 4));
}

// ---------------- router: logits + top8 + counts + x->fp16 ----------------
#define RT 8
__global__ void router_kernel(const float* __restrict__ x, const float* __restrict__ gate) {
    __shared__ float xs[RT][HID];
    __shared__ float lg[RT][NEXP];
    int t0 = blockIdx.x * RT;
    int tid = threadIdx.x;  // 256
    const float4* xsrc = (const float4*)(x + (size_t)t0 * HID);
    for (int i = tid; i < RT * HID / 4; i += 256) ((float4*)&xs[0][0])[i] = xsrc[i];
    __syncthreads();
    // write fp16 copy of these 8 token rows (same rounding gemm1 used before)
    for (int i = tid; i < RT * HID / 4; i += 256) {
        float4 f = ((const float4*)&xs[0][0])[i];
        uint32_t h0, h1; cvt4h(f, h0, h1);
        uint2* dst = (uint2*)(g_xh + (size_t)t0 * HID) + i;
        *dst = make_uint2(h0, h1);
    }
    int tt = tid >> 5, lane = tid & 31;
    #pragma unroll
    for (int g = 0; g < 2; g++) {
        int e = g * 32 + lane;
        const float* gp = gate + (size_t)e * HID;
        float s = 0.f;
        #pragma unroll 4
        for (int k = 0; k < HID; k += 4) {
            float4 gv = *(const float4*)(gp + k);
            s += xs[tt][k] * gv.x + xs[tt][k+1] * gv.y + xs[tt][k+2] * gv.z + xs[tt][k+3] * gv.w;
        }
        lg[tt][e] = s;
    }
    __syncthreads();
    if (tid < RT) {
        int t = t0 + tid;
        float mx = lg[tid][0];
        #pragma unroll
        for (int e = 1; e < NEXP; e++) mx = fmaxf(mx, lg[tid][e]);
        unsigned long long taken = 0ull;
        float wsum = 0.f;
        int sel[TOPK]; float wv[TOPK];
        for (int k = 0; k < TOPK; k++) {
            int best = 0; float bv = -1e30f;
            for (int e = 0; e < NEXP; e++) {
                float v = lg[tid][e];
                if (!((taken >> e) & 1ull) && v > bv) { bv = v; best = e; }
            }
            taken |= 1ull << best;
            sel[k] = best;
            float w = expf(lg[tid][best] - mx);
            wv[k] = w; wsum += w;
            atomicAdd(&g_counts[best], 1);
        }
        float inv = 1.f / wsum;
        for (int k = 0; k < TOPK; k++) {
            g_topkw[t * TOPK + k]   = wv[k] * inv;
            g_flatexp[t * TOPK + k] = sel[k];
        }
    }
}

// ---------------- meta: offsets + tile table (+ first-run rowtok fill) ----------------
__global__ void meta_kernel() {
    int tid = threadIdx.x;   // 256
    if (g_first == 0) {      // only the very first run; combine maintains it afterwards
        for (int i = tid; i < MPAD; i += 256) g_rowtok[i] = -1;
    }
    __syncthreads();
    if (tid == 0) {
        g_first = 1;
        int nt = 0, cum = 0;
        for (int e = 0; e < NEXP; e++) {
            g_offpad[e] = cum;
            int c = g_counts[e];
            int t = (c + BM - 1) / BM;
            for (int j = 0; j < t; j++) { g_tile_e[nt] = e; g_tile_r0[nt] = cum + j * BM; nt++; }
            cum += t * BM;
        }
        g_ntiles = nt;
    }
}

// ---------------- scatter: parallel counting-sort placement ----------------
__global__ void scatter_kernel() {
    int i = blockIdx.x * 256 + threadIdx.x;
    if (i >= FLAT) return;
    int e = g_flatexp[i];
    int dest = g_offpad[e] + atomicAdd(&g_ctr[e], 1);
    g_rowtok[dest] = i >> 3;
    g_invperm[i] = dest;
}

// ---------------- grouped GEMM: single fp16 everywhere, KC=16, 2 CTA/SM -------------
// CTA: 256 thr = 8 warps (2x4), tile M=128 x N=128, warp tile 64x32. grid(nb, tile).
// A: fp16 (g_xh gathered for GEMM1 / g_inter direct for GEMM2), straight 16B copy.
// B: fp32 weights, cvt to fp16 while staging.

#define BUF_SZ  8192
#define OFF_B   4096
#define SMEM_BYTES 32768

template<bool FUSED>
__global__ void __launch_bounds__(256, 2) moe_gemm(const float* __restrict__ W) {
    constexpr int KDIM = FUSED ? HID : IDIM;   // 1024 / 768
    constexpr int NK   = KDIM / 16;            // 64 / 48
    int nb   = blockIdx.x;
    int tile = blockIdx.y;
    if (tile >= g_ntiles) return;
    int e = g_tile_e[tile], row0 = g_tile_r0[tile];

    extern __shared__ __align__(128) char smem[];
    uint32_t sb = smem_u32(smem);

    int tid = threadIdx.x, lane = tid & 31, wid = tid >> 5;
    int wm = wid >> 2, wn = wid & 3;

    // -------- B copy mapping: rows r0/r1, ch16 = tid&3 (fp32 -> fp16 cvt)
    int r0 = tid >> 2, r1 = r0 + 64, ch = tid & 3;
    uint32_t soff0 = swz16(r0, ch >> 1) + (uint32_t)((ch & 1) * 8);
    uint32_t soff1 = swz16(r1, ch >> 1) + (uint32_t)((ch & 1) * 8);

    // -------- A fp16 copy mapping: row = tid/2, 16B chunk = tid&1
    int rh = tid >> 1, chh = tid & 1;
    uint32_t soffh = swz16(rh, chh);

    const __half* aptrh;
    if (FUSED) {
        int tok = g_rowtok[row0 + rh];
        aptrh = (tok >= 0) ? g_xh + (size_t)tok * HID + chh * 8 : nullptr;
    } else {
        aptrh = g_inter + (size_t)(row0 + rh) * IDIM + chh * 8;
    }
    const float* Wb = W + (size_t)e * (size_t)(FUSED ? 2 * IDIM : HID) * KDIM;
    int wr0 = FUSED ? (nb * 64 + r0) : (nb * 128 + r0);            // r0 in 0..63
    int wr1 = FUSED ? (IDIM + nb * 64 + (r1 - 64)) : (nb * 128 + r1);
    const float* bptr0 = Wb + (size_t)wr0 * KDIM + ch * 4;
    const float* bptr1 = Wb + (size_t)wr1 * KDIM + ch * 4;

    float acc[4][4][4];
    #pragma unroll
    for (int a = 0; a < 4; a++)
        #pragma unroll
        for (int b = 0; b < 4; b++)
            #pragma unroll
            for (int c = 0; c < 4; c++) acc[a][b][c] = 0.f;

    const uint4 ZH = make_uint4(0u, 0u, 0u, 0u);
    float4 pb0, pb1;
    uint4 pah;
    // prefetch kt = 0
    pah = aptrh ? *(const uint4*)(aptrh) : ZH;
    pb0 = *(const float4*)(bptr0);
    pb1 = *(const float4*)(bptr1);
    // fill buffer 0
    {
        uint32_t h0, h1;
        STS128(sb + soffh, pah);
        cvt4h(pb0, h0, h1); STS64(sb + OFF_B + soff0, h0, h1);
        cvt4h(pb1, h0, h1); STS64(sb + OFF_B + soff1, h0, h1);
    }
    __syncthreads();

    #pragma unroll 1
    for (int kt = 0; kt < NK; kt++) {
        uint32_t cur = sb + (uint32_t)((kt & 1) * BUF_SZ);
        // issue next-tile LDGs early
        if (kt + 1 < NK) {
            int ko = (kt + 1) * 16;
            pah = aptrh ? *(const uint4*)(aptrh + ko) : ZH;
            pb0 = *(const float4*)(bptr0 + ko);
            pb1 = *(const float4*)(bptr1 + ko);
        }

        // -------- compute one k=16 slab (warp tile 64x32, single fp16)
        {
            uint32_t aH[4][4];
            #pragma unroll
            for (int mt = 0; mt < 4; mt++) {
                int row = wm * 64 + mt * 16 + (lane & 15);
                uint32_t ad = swz16(row, lane >> 4);
                ldsm_x4(aH[mt], cur + ad);
            }
            #pragma unroll
            for (int np = 0; np < 2; np++) {
                int row = wn * 32 + np * 16 + (lane & 7) + ((lane >> 4) << 3);
                uint32_t bd = swz16(row, (lane >> 3) & 1);
                uint32_t tH[4];
                ldsm_x4(tH, cur + OFF_B + bd);
                uint32_t bH0[2] = {tH[0], tH[1]}, bH1[2] = {tH[2], tH[3]};
                #pragma unroll
                for (int mt = 0; mt < 4; mt++) {
                    mma16816(acc[mt][2*np],   aH[mt], bH0);
                    mma16816(acc[mt][2*np+1], aH[mt], bH1);
                }
            }
        }

        // stage next slab into the other buffer
        if (kt + 1 < NK) {
            uint32_t nxt = sb + (uint32_t)(((kt + 1) & 1) * BUF_SZ);
            uint32_t h0, h1;
            STS128(nxt + soffh, pah);
            cvt4h(pb0, h0, h1); STS64(nxt + OFF_B + soff0, h0, h1);
            cvt4h(pb1, h0, h1); STS64(nxt + OFF_B + soff1, h0, h1);
        }
        __syncthreads();
    }

    if (FUSED) {
        float* sUp = (float*)smem;   // [128][64] f32 = 32KB
        if (wn >= 2) {
            #pragma unroll
            for (int mt = 0; mt < 4; mt++)
                #pragma unroll
                for (int nt = 0; nt < 4; nt++) {
                    int m = wm * 64 + mt * 16 + (lane >> 2);
                    int c = (wn - 2) * 32 + nt * 8 + (lane & 3) * 2;
                    sUp[m * 64 + c]           = acc[mt][nt][0];
                    sUp[m * 64 + c + 1]       = acc[mt][nt][1];
                    sUp[(m + 8) * 64 + c]     = acc[mt][nt][2];
                    sUp[(m + 8) * 64 + c + 1] = acc[mt][nt][3];
                }
        }
        __syncthreads();
        if (wn < 2) {
            #pragma unroll
            for (int mt = 0; mt < 4; mt++)
                #pragma unroll
                for (int nt = 0; nt < 4; nt++) {
                    int m = wm * 64 + mt * 16 + (lane >> 2);
                    int c = wn * 32 + nt * 8 + (lane & 3) * 2;
                    #pragma unroll
                    for (int h = 0; h < 2; h++) {
                        int mm = m + h * 8;
                        float g0 = acc[mt][nt][h * 2], g1 = acc[mt][nt][h * 2 + 1];
                        float u0 = sUp[mm * 64 + c], u1 = sUp[mm * 64 + c + 1];
                        float o0 = g0 / (1.f + expf(-g0)) * u0;
                        float o1 = g1 / (1.f + expf(-g1)) * u1;
                        __half2 hp = __floats2half2_rn(o0, o1);
                        *(uint32_t*)&g_inter[(size_t)(row0 + mm) * IDIM + nb * 64 + c] = *(uint32_t*)&hp;
                    }
                }
        }
    } else {
        #pragma unroll
        for (int mt = 0; mt < 4; mt++)
            #pragma unroll
            for (int nt = 0; nt < 4; nt++) {
                int m = row0 + wm * 64 + mt * 16 + (lane >> 2);
                int c = nb * 128 + wn * 32 + nt * 8 + (lane & 3) * 2;
                __half2 h0 = __floats2half2_rn(acc[mt][nt][0], acc[mt][nt][1]);
                __half2 h1 = __floats2half2_rn(acc[mt][nt][2], acc[mt][nt][3]);
                *(uint32_t*)&g_y2[(size_t)m * HID + c]       = *(uint32_t*)&h0;
                *(uint32_t*)&g_y2[(size_t)(m + 8) * HID + c] = *(uint32_t*)&h1;
            }
    }
}

// ---------------- combine (y2 fp16) + per-run state reset for next replay ----------------
__global__ void combine_kernel(float* __restrict__ out) {
    __shared__ float w[TOPK];
    __shared__ int rows[TOPK];
    int t = blockIdx.x;
    int tid = threadIdx.x;   // 256, 4 cols each
    if (tid < TOPK) {
        w[tid]    = g_topkw[t * TOPK + tid];
        rows[tid] = g_invperm[t * TOPK + tid];
    }
    __syncthreads();
    float4 acc = make_float4(0.f, 0.f, 0.f, 0.f);
    #pragma unroll
    for (int k = 0; k < TOPK; k++) {
        uint2 v = *(const uint2*)&g_y2[(size_t)rows[k] * HID + (tid << 2)];
        __half2 a = *(__half2*)&v.x;
        __half2 b = *(__half2*)&v.y;
        float2 fa = __half22float2(a), fb = __half22float2(b);
        float wk = w[k];
        acc.x += wk * fa.x; acc.y += wk * fa.y; acc.z += wk * fb.x; acc.w += wk * fb.y;
    }
    *(float4*)(out + (size_t)t * HID + (tid << 2)) = acc;

    // reset routing state for the next (identical) run
    int gid = t * 256 + tid;
    if (gid < NEXP) { g_counts[gid] = 0; g_ctr[gid] = 0; }
    if (gid < MPAD) g_rowtok[gid] = -1;
}

// ---------------- launch ----------------
extern "C" void kernel_launch(void* const* d_in, const int* in_sizes, int n_in,
                              void* d_out, int out_size) {
    const float* x    = (const float*)d_in[0];
    const float* gate = (const float*)d_in[1];
    const float* gup  = (const float*)d_in[2];
    const float* dwn  = (const float*)d_in[3];
    float* out = (float*)d_out;

    cudaFuncSetAttribute(moe_gemm<true>,  cudaFuncAttributeMaxDynamicSharedMemorySize, SMEM_BYTES);
    cudaFuncSetAttribute(moe_gemm<false>, cudaFuncAttributeMaxDynamicSharedMemorySize, SMEM_BYTES);

    router_kernel<<<NTOK / RT, 256>>>(x, gate);                               // launch 0
    meta_kernel<<<1, 256>>>();                                                // launch 1
    scatter_kernel<<<FLAT / 256, 256>>>();                                    // launch 2
    moe_gemm<true><<<dim3(IDIM / 64, MAXTILES), 256, SMEM_BYTES>>>(gup);      // launch 3 (profiled)
    moe_gemm<false><<<dim3(HID / 128, MAXTILES), 256, SMEM_BYTES>>>(dwn);     // launch 4
    combine_kernel<<<NTOK, 256>>>(out);                                       // launch 5
}